// round 11
// baseline (speedup 1.0000x reference)
#include <cuda_runtime.h>
#include <cuda_fp16.h>
#include <stdint.h>

// Problem constants
#define Bd   2
#define Nseq 2048
#define Dm   1024
#define Hh   16
#define HD   64
#define SCALE 0.125f
#define Kdim 1024

// ---------------- device scratch (no allocations allowed) -------------------
__device__ __half g_x[Bd*Nseq*Dm];          // x fp16
__device__ __half g_wq[3*Dm*Kdim];          // w_qkv^T fp16 [3072,1024]
__device__ __half g_wp[Dm*Kdim];            // w_proj^T fp16 [1024,1024]
__device__ __half g_q[Bd*Hh*Nseq*HD];       // q*scale fp16 [B,H,N,64]
__device__ __half g_k[Bd*Hh*Nseq*HD];
__device__ __half g_v[Bd*Hh*Nseq*HD];
__device__ __half g_a[Bd*Nseq*Dm];          // attention out fp16

// ---------------- helpers ----------------------------------------------------
__device__ __forceinline__ uint32_t smem_u32(const void* p) {
    return (uint32_t)__cvta_generic_to_shared(p);
}
__device__ __forceinline__ void mma_f16(float (&d)[4], const uint32_t (&a)[4],
                                        const uint32_t (&b)[2]) {
    asm volatile(
        "mma.sync.aligned.m16n8k16.row.col.f32.f16.f16.f32 "
        "{%0,%1,%2,%3}, {%4,%5,%6,%7}, {%8,%9}, {%0,%1,%2,%3};"
        : "+f"(d[0]), "+f"(d[1]), "+f"(d[2]), "+f"(d[3])
        : "r"(a[0]), "r"(a[1]), "r"(a[2]), "r"(a[3]), "r"(b[0]), "r"(b[1]));
}
__device__ __forceinline__ void ldsm4(uint32_t (&r)[4], uint32_t addr) {
    asm volatile("ldmatrix.sync.aligned.m8n8.x4.shared.b16 {%0,%1,%2,%3}, [%4];"
        : "=r"(r[0]), "=r"(r[1]), "=r"(r[2]), "=r"(r[3]) : "r"(addr));
}
__device__ __forceinline__ void ldsm4t(uint32_t (&r)[4], uint32_t addr) {
    asm volatile("ldmatrix.sync.aligned.m8n8.x4.trans.shared.b16 {%0,%1,%2,%3}, [%4];"
        : "=r"(r[0]), "=r"(r[1]), "=r"(r[2]), "=r"(r[3]) : "r"(addr));
}
__device__ __forceinline__ uint32_t pack_f16(float lo, float hi) {
    __half2 h = __floats2half2_rn(lo, hi);
    return *(uint32_t*)&h;
}
__device__ __forceinline__ void cp16(uint32_t s, const void* g) {
    asm volatile("cp.async.cg.shared.global [%0], [%1], 16;" :: "r"(s), "l"(g));
}
#define CP_COMMIT() asm volatile("cp.async.commit_group;" ::: "memory")
#define CP_WAIT1()  asm volatile("cp.async.wait_group 1;" ::: "memory")
#define CP_WAIT0()  asm volatile("cp.async.wait_group 0;" ::: "memory")

// ---------------- convert pre-passes -----------------------------------------
__global__ void __launch_bounds__(256) conv_x_kernel(const float* __restrict__ x) {
    int i4 = (blockIdx.x * 256 + threadIdx.x) * 4;
    if (i4 >= Bd * Nseq * Dm) return;
    float4 v = *(const float4*)&x[i4];
    *(__half2*)&g_x[i4]     = __floats2half2_rn(v.x, v.y);
    *(__half2*)&g_x[i4 + 2] = __floats2half2_rn(v.z, v.w);
}

template<int WHICH>  // 0: qkv, 1: proj
__global__ void __launch_bounds__(256) convT_kernel(const float* __restrict__ w, int N) {
    __shared__ float t[32][33];
    int tx = threadIdx.x & 31, ty = threadIdx.x >> 5;   // 32 x 8
    int n0 = blockIdx.x * 32, k0 = blockIdx.y * 32;
    #pragma unroll
    for (int i = 0; i < 4; i++) {
        int k = k0 + ty + i * 8;
        t[ty + i * 8][tx] = w[(size_t)k * N + n0 + tx];
    }
    __syncthreads();
    __half* dst = WHICH ? g_wp : g_wq;
    #pragma unroll
    for (int i = 0; i < 4; i++) {
        int n = n0 + ty + i * 8;
        dst[(size_t)n * Kdim + k0 + tx] = __float2half_rn(t[tx][ty + i * 8]);
    }
}

// ---------------- HMMA GEMM: fp16, 256 thr, 128x64 tile, 3 CTA/SM -----------
// 8 warps (4m x 2n), warp tile 32x32, K-tile 32, cp.async 3-stage.
// Stage (15360 B): A[128 rows x 80B pitch] + B[64 rows x 80B pitch]
#define GSTAGE 15360
#define GEMM_DSMEM (3 * GSTAGE)
#define GEMM_NT (Kdim / 32)

template<int MODE>
__global__ void __launch_bounds__(256, 3) mma_gemm(const float* __restrict__ bias,
                                                   float* __restrict__ C, int Nc) {
    extern __shared__ char dyn[];
    const uint32_t sbase = smem_u32(dyn);

    const int tid = threadIdx.x, lane = tid & 31, wid = tid >> 5;
    const int m0 = blockIdx.y * 128, n0 = blockIdx.x * 64;
    const __half* A = MODE ? g_x : g_a;
    const __half* B = MODE ? g_wq : g_wp;
    const int wm = (wid >> 1) * 32, wn = (wid & 1) * 32;

    float acc[2][4][4] = {};

    const uint32_t lmr = (uint32_t)(lane & 15);
    const uint32_t lmc = (uint32_t)((lane >> 4) * 16);

    // fill: 768 cp16 slots = 192 rows (128 A + 64 B) x 4 chunks; 3 per thread
    auto fill = [&](int st, int k0) {
        uint32_t sb = sbase + st * GSTAGE;
        #pragma unroll
        for (int l = 0; l < 3; l++) {
            int s = tid + l * 256;
            int r = s >> 2, c = s & 3;
            if (r < 128) {
                cp16(sb + (uint32_t)(r * 80 + c * 16),
                     &A[(size_t)(m0 + r) * Kdim + k0 + c * 8]);
            } else {
                cp16(sb + 10240 + (uint32_t)((r - 128) * 80 + c * 16),
                     &B[(size_t)(n0 + r - 128) * Kdim + k0 + c * 8]);
            }
        }
    };

    fill(0, 0);  CP_COMMIT();
    fill(1, 32); CP_COMMIT();

    for (int t = 0; t < GEMM_NT; t++) {
        if (t + 2 < GEMM_NT) CP_WAIT1(); else CP_WAIT0();
        __syncthreads();
        if (t + 2 < GEMM_NT) { fill((t + 2) % 3, (t + 2) * 32); CP_COMMIT(); }

        const uint32_t sb = sbase + (t % 3) * GSTAGE;
        const uint32_t aA = sb, aB = sb + 10240;

        #pragma unroll
        for (int kt = 0; kt < 2; kt++) {
            uint32_t a[2][4], b[4][2];
            #pragma unroll
            for (int mi = 0; mi < 2; mi++) {
                uint32_t ro = (wm + mi * 16 + lmr) * 80 + kt * 32 + lmc;
                ldsm4(a[mi], aA + ro);
            }
            #pragma unroll
            for (int g = 0; g < 2; g++) {
                uint32_t ro = (wn + g * 16 + lmr) * 80 + kt * 32 + lmc;
                uint32_t tt[4];
                ldsm4(tt, aB + ro);
                b[2*g][0] = tt[0]; b[2*g][1] = tt[2];
                b[2*g+1][0] = tt[1]; b[2*g+1][1] = tt[3];
            }
            #pragma unroll
            for (int mi = 0; mi < 2; mi++)
                #pragma unroll
                for (int ni = 0; ni < 4; ni++)
                    mma_f16(acc[mi][ni], a[mi], b[ni]);
        }
    }

    // epilogue
    #pragma unroll
    for (int mi = 0; mi < 2; mi++) {
        int r0 = m0 + wm + mi * 16 + (lane >> 2);
        #pragma unroll
        for (int ni = 0; ni < 4; ni++) {
            int col = n0 + wn + ni * 8 + 2 * (lane & 3);
            float b0 = bias[col], b1 = bias[col + 1];
            #pragma unroll
            for (int rr = 0; rr < 2; rr++) {
                int row = r0 + rr * 8;
                float v0 = acc[mi][ni][rr * 2 + 0] + b0;
                float v1 = acc[mi][ni][rr * 2 + 1] + b1;
                if (MODE == 0) {
                    *(float2*)&C[(size_t)row * Nc + col] = make_float2(v0, v1);
                } else {
                    int bb = row >> 11, nn = row & 2047;
                    int which = col >> 10, rem = col & 1023;
                    int hh = rem >> 6, dd = rem & 63;
                    if (which == 0) { v0 *= SCALE; v1 *= SCALE; }
                    size_t idx = (((size_t)(bb * Hh + hh)) * Nseq + nn) * HD + dd;
                    __half* dst = (which == 0) ? g_q : (which == 1) ? g_k : g_v;
                    *(__half2*)&dst[idx] = __floats2half2_rn(v0, v1);
                }
            }
        }
    }
}

// ---------------- flash attention: fp16, cp.async 3-stage, 2 CTA/SM ----------
// 8 warps, Q-tile 128 (Q in registers), K-tile 64. Rows 128B fp16, pitch 144B.
#define FSTAGE 18432
#define FLASH_DSMEM (3 * FSTAGE + 3 * 256)
#define FLASH_NT (Nseq / 64)

__global__ void __launch_bounds__(256, 2) flash_mma(const float* __restrict__ attn_bias) {
    extern __shared__ char dyn[];
    const uint32_t sbase = smem_u32(dyn);
    const uint32_t sbias = sbase + 3 * FSTAGE;

    const int tid = threadIdx.x, lane = tid & 31, wid = tid >> 5;
    const int b = blockIdx.z, h = blockIdx.y, q0 = blockIdx.x * 128;
    const size_t hoff = (size_t)((b * Hh + h) * Nseq) * HD;
    const __half *Qp = g_q + hoff, *Kp = g_k + hoff, *Vp = g_v + hoff;
    const float* biasg = attn_bias + b * Nseq;

    const int fr = tid >> 3, fc = tid & 7;   // row base (0..31), 16B chunk (0..7)

    auto fill = [&](int st, int k0) {
        uint32_t sb = sbase + st * FSTAGE;
        #pragma unroll
        for (int half = 0; half < 2; half++) {
            int r = fr + half * 32;
            uint32_t o = (uint32_t)(r * 144 + fc * 16);
            size_t g = (size_t)(k0 + r) * HD + fc * 8;
            cp16(sb + o,        &Kp[g]);
            cp16(sb + 9216 + o, &Vp[g]);
        }
        if (tid < 16) cp16(sbias + st * 256 + tid * 16, &biasg[k0 + tid * 4]);
    };

    // ---- Q A-fragments directly from gmem ----
    uint32_t qf[4][4];
    {
        int r = q0 + wid * 16 + (lane >> 2);
        int c = 2 * (lane & 3);
        #pragma unroll
        for (int kf = 0; kf < 4; kf++) {
            #pragma unroll
            for (int e = 0; e < 4; e++) {
                size_t g = (size_t)(r + (e & 1) * 8) * HD + kf * 16 + (e >> 1) * 8 + c;
                qf[kf][e] = *(const uint32_t*)&Qp[g];
            }
        }
    }

    fill(0, 0);  CP_COMMIT();
    fill(1, 64); CP_COMMIT();

    float O[8][4] = {};
    float mrow0 = -1e30f, mrow1 = -1e30f, lrow0 = 0.f, lrow1 = 0.f;

    for (int t = 0; t < FLASH_NT; t++) {
        if (t + 2 < FLASH_NT) CP_WAIT1(); else CP_WAIT0();
        __syncthreads();
        if (t + 2 < FLASH_NT) { fill((t + 2) % 3, (t + 2) * 64); CP_COMMIT(); }

        const uint32_t sb = sbase + (t % 3) * FSTAGE;
        const uint32_t aK = sb, aV = sb + 9216;
        const float* sB = (const float*)(dyn + 3 * FSTAGE + (t % 3) * 256);

        // ---- S = Q K^T ----
        float S[8][4] = {};
        #pragma unroll
        for (int kf = 0; kf < 4; kf++) {
            #pragma unroll
            for (int g = 0; g < 4; g++) {
                uint32_t ro = (uint32_t)((g * 16 + (lane & 15)) * 144 + kf * 32 + (lane >> 4) * 16);
                uint32_t tt[4], b0[2], b1[2];
                ldsm4(tt, aK + ro);
                b0[0] = tt[0]; b0[1] = tt[2]; b1[0] = tt[1]; b1[1] = tt[3];
                mma_f16(S[2*g],   qf[kf], b0);
                mma_f16(S[2*g+1], qf[kf], b1);
            }
        }

        // ---- bias + online softmax ----
        float mx0 = mrow0, mx1 = mrow1;
        #pragma unroll
        for (int nt = 0; nt < 8; nt++) {
            float2 bb = *(const float2*)&sB[nt * 8 + 2 * (lane & 3)];
            S[nt][0] += bb.x; S[nt][1] += bb.y;
            S[nt][2] += bb.x; S[nt][3] += bb.y;
            mx0 = fmaxf(mx0, fmaxf(S[nt][0], S[nt][1]));
            mx1 = fmaxf(mx1, fmaxf(S[nt][2], S[nt][3]));
        }
        mx0 = fmaxf(mx0, __shfl_xor_sync(0xffffffffu, mx0, 1));
        mx0 = fmaxf(mx0, __shfl_xor_sync(0xffffffffu, mx0, 2));
        mx1 = fmaxf(mx1, __shfl_xor_sync(0xffffffffu, mx1, 1));
        mx1 = fmaxf(mx1, __shfl_xor_sync(0xffffffffu, mx1, 2));
        float alpha0 = __expf(mrow0 - mx0), alpha1 = __expf(mrow1 - mx1);
        mrow0 = mx0; mrow1 = mx1;
        float sum0 = 0.f, sum1 = 0.f;
        #pragma unroll
        for (int nt = 0; nt < 8; nt++) {
            S[nt][0] = __expf(S[nt][0] - mx0); S[nt][1] = __expf(S[nt][1] - mx0);
            S[nt][2] = __expf(S[nt][2] - mx1); S[nt][3] = __expf(S[nt][3] - mx1);
            sum0 += S[nt][0] + S[nt][1];
            sum1 += S[nt][2] + S[nt][3];
        }
        sum0 += __shfl_xor_sync(0xffffffffu, sum0, 1);
        sum0 += __shfl_xor_sync(0xffffffffu, sum0, 2);
        sum1 += __shfl_xor_sync(0xffffffffu, sum1, 1);
        sum1 += __shfl_xor_sync(0xffffffffu, sum1, 2);
        lrow0 = lrow0 * alpha0 + sum0;
        lrow1 = lrow1 * alpha1 + sum1;
        #pragma unroll
        for (int dt = 0; dt < 8; dt++) {
            O[dt][0] *= alpha0; O[dt][1] *= alpha0;
            O[dt][2] *= alpha1; O[dt][3] *= alpha1;
        }

        // ---- P -> fp16 A-fragments ----
        uint32_t pf[4][4];
        #pragma unroll
        for (int kt = 0; kt < 4; kt++) {
            #pragma unroll
            for (int half = 0; half < 2; half++) {
                int nt = 2 * kt + half;
                pf[kt][half * 2 + 0] = pack_f16(S[nt][0], S[nt][1]);
                pf[kt][half * 2 + 1] = pack_f16(S[nt][2], S[nt][3]);
            }
        }

        // ---- O += P V ----
        #pragma unroll
        for (int kt = 0; kt < 4; kt++) {
            #pragma unroll
            for (int g = 0; g < 4; g++) {
                uint32_t ro = (uint32_t)((kt * 16 + (lane & 7) + 8 * ((lane >> 3) & 1)) * 144
                                         + g * 32 + (lane >> 4) * 16);
                uint32_t tt[4], v0[2], v1[2];
                ldsm4t(tt, aV + ro);
                v0[0] = tt[0]; v0[1] = tt[1]; v1[0] = tt[2]; v1[1] = tt[3];
                mma_f16(O[2*g],   pf[kt], v0);
                mma_f16(O[2*g+1], pf[kt], v1);
            }
        }
    }

    // ---- epilogue: normalize, write fp16 attention output ----
    float inv0 = 1.f / lrow0, inv1 = 1.f / lrow1;
    int r0 = q0 + wid * 16 + (lane >> 2);
    #pragma unroll
    for (int dt = 0; dt < 8; dt++) {
        int col = h * HD + dt * 8 + 2 * (lane & 3);
        size_t i0 = (size_t)(b * Nseq + r0) * Dm + col;
        size_t i1 = (size_t)(b * Nseq + r0 + 8) * Dm + col;
        *(__half2*)&g_a[i0] = __floats2half2_rn(O[dt][0] * inv0, O[dt][1] * inv0);
        *(__half2*)&g_a[i1] = __floats2half2_rn(O[dt][2] * inv1, O[dt][3] * inv1);
    }
}

// ---------------- launch -----------------------------------------------------
extern "C" void kernel_launch(void* const* d_in, const int* in_sizes, int n_in,
                              void* d_out, int out_size)
{
    const float* x         = (const float*)d_in[0];
    const float* attn_bias = (const float*)d_in[1];
    const float* w_qkv     = (const float*)d_in[2];
    const float* b_qkv     = (const float*)d_in[3];
    const float* w_proj    = (const float*)d_in[4];
    const float* b_proj    = (const float*)d_in[5];
    float* out = (float*)d_out;

    cudaFuncSetAttribute(mma_gemm<1>, cudaFuncAttributeMaxDynamicSharedMemorySize, GEMM_DSMEM);
    cudaFuncSetAttribute(mma_gemm<0>, cudaFuncAttributeMaxDynamicSharedMemorySize, GEMM_DSMEM);
    cudaFuncSetAttribute(flash_mma,   cudaFuncAttributeMaxDynamicSharedMemorySize, FLASH_DSMEM);

    conv_x_kernel<<<(Bd * Nseq * Dm) / (256 * 4), 256>>>(x);
    convT_kernel<0><<<dim3(3 * Dm / 32, Kdim / 32), 256>>>(w_qkv, 3 * Dm);
    convT_kernel<1><<<dim3(Dm / 32, Kdim / 32), 256>>>(w_proj, Dm);

    mma_gemm<1><<<dim3(3 * Dm / 64, (Bd * Nseq) / 128), 256, GEMM_DSMEM>>>(b_qkv, nullptr, 3 * Dm);

    flash_mma<<<dim3(Nseq / 128, Hh, Bd), 256, FLASH_DSMEM>>>(attn_bias);

    mma_gemm<0><<<dim3(Dm / 64, (Bd * Nseq) / 128), 256, GEMM_DSMEM>>>(b_proj, out, Dm);
}

// round 12
// speedup vs baseline: 1.0071x; 1.0071x over previous
#include <cuda_runtime.h>
#include <cuda_fp16.h>
#include <stdint.h>

// Problem constants
#define Bd   2
#define Nseq 2048
#define Dm   1024
#define Hh   16
#define HD   64
#define SCALE 0.125f
#define Kdim 1024

// ---------------- device scratch (no allocations allowed) -------------------
__device__ __half g_x[Bd*Nseq*Dm];          // x fp16
__device__ __half g_wq[3*Dm*Kdim];          // w_qkv^T fp16 [3072,1024]
__device__ __half g_wp[Dm*Kdim];            // w_proj^T fp16 [1024,1024]
__device__ __half g_q[Bd*Hh*Nseq*HD];       // q*scale fp16 [B,H,N,64]
__device__ __half g_k[Bd*Hh*Nseq*HD];
__device__ __half g_v[Bd*Hh*Nseq*HD];
__device__ __half g_a[Bd*Nseq*Dm];          // attention out fp16

// ---------------- helpers ----------------------------------------------------
__device__ __forceinline__ uint32_t smem_u32(const void* p) {
    return (uint32_t)__cvta_generic_to_shared(p);
}
__device__ __forceinline__ void mma_f16(float (&d)[4], const uint32_t (&a)[4],
                                        const uint32_t (&b)[2]) {
    asm volatile(
        "mma.sync.aligned.m16n8k16.row.col.f32.f16.f16.f32 "
        "{%0,%1,%2,%3}, {%4,%5,%6,%7}, {%8,%9}, {%0,%1,%2,%3};"
        : "+f"(d[0]), "+f"(d[1]), "+f"(d[2]), "+f"(d[3])
        : "r"(a[0]), "r"(a[1]), "r"(a[2]), "r"(a[3]), "r"(b[0]), "r"(b[1]));
}
__device__ __forceinline__ void ldsm4(uint32_t (&r)[4], uint32_t addr) {
    asm volatile("ldmatrix.sync.aligned.m8n8.x4.shared.b16 {%0,%1,%2,%3}, [%4];"
        : "=r"(r[0]), "=r"(r[1]), "=r"(r[2]), "=r"(r[3]) : "r"(addr));
}
__device__ __forceinline__ void ldsm4t(uint32_t (&r)[4], uint32_t addr) {
    asm volatile("ldmatrix.sync.aligned.m8n8.x4.trans.shared.b16 {%0,%1,%2,%3}, [%4];"
        : "=r"(r[0]), "=r"(r[1]), "=r"(r[2]), "=r"(r[3]) : "r"(addr));
}
__device__ __forceinline__ uint32_t pack_f16(float lo, float hi) {
    __half2 h = __floats2half2_rn(lo, hi);
    return *(uint32_t*)&h;
}
__device__ __forceinline__ void cp16(uint32_t s, const void* g) {
    asm volatile("cp.async.cg.shared.global [%0], [%1], 16;" :: "r"(s), "l"(g));
}
#define CP_COMMIT() asm volatile("cp.async.commit_group;" ::: "memory")
#define CP_WAIT1()  asm volatile("cp.async.wait_group 1;" ::: "memory")
#define CP_WAIT0()  asm volatile("cp.async.wait_group 0;" ::: "memory")

// ---------------- convert pre-passes -----------------------------------------
__global__ void __launch_bounds__(256) conv_x_kernel(const float* __restrict__ x) {
    int i4 = (blockIdx.x * 256 + threadIdx.x) * 4;
    if (i4 >= Bd * Nseq * Dm) return;
    float4 v = *(const float4*)&x[i4];
    *(__half2*)&g_x[i4]     = __floats2half2_rn(v.x, v.y);
    *(__half2*)&g_x[i4 + 2] = __floats2half2_rn(v.z, v.w);
}

template<int WHICH>  // 0: qkv, 1: proj
__global__ void __launch_bounds__(256) convT_kernel(const float* __restrict__ w, int N) {
    __shared__ float t[32][33];
    int tx = threadIdx.x & 31, ty = threadIdx.x >> 5;   // 32 x 8
    int n0 = blockIdx.x * 32, k0 = blockIdx.y * 32;
    #pragma unroll
    for (int i = 0; i < 4; i++) {
        int k = k0 + ty + i * 8;
        t[ty + i * 8][tx] = w[(size_t)k * N + n0 + tx];
    }
    __syncthreads();
    __half* dst = WHICH ? g_wp : g_wq;
    #pragma unroll
    for (int i = 0; i < 4; i++) {
        int n = n0 + ty + i * 8;
        dst[(size_t)n * Kdim + k0 + tx] = __float2half_rn(t[tx][ty + i * 8]);
    }
}

// ---------------- HMMA GEMM: fp16, 256 thr, 128x128 tile, warp 32x64 --------
// 8 warps (4m x 2n), warp tile 32x64: 6 LDSM feed 16 MMAs per kt; both kt's
// fragments preloaded -> 32-MMA independent burst per K-tile. 2 CTA/SM.
// Stage (20480 B): A[128 rows x 80B pitch] + B[128 rows x 80B pitch]
#define GSTAGE 20480
#define GEMM_DSMEM (3 * GSTAGE)
#define GEMM_NT (Kdim / 32)

template<int MODE>
__global__ void __launch_bounds__(256, 2) mma_gemm(const float* __restrict__ bias,
                                                   float* __restrict__ C, int Nc) {
    extern __shared__ char dyn[];
    const uint32_t sbase = smem_u32(dyn);

    const int tid = threadIdx.x, lane = tid & 31, wid = tid >> 5;
    const int m0 = blockIdx.y * 128, n0 = blockIdx.x * 128;
    const __half* A = MODE ? g_x : g_a;
    const __half* B = MODE ? g_wq : g_wp;
    const int wm = (wid >> 1) * 32, wn = (wid & 1) * 64;

    float acc[2][8][4] = {};

    const uint32_t lmr = (uint32_t)(lane & 15);
    const uint32_t lmc = (uint32_t)((lane >> 4) * 16);
    // hoisted ldsm bases (relative to stage start)
    const uint32_t roA = (uint32_t)((wm + lmr) * 80) + lmc;           // + mi*1280 + kt*32
    const uint32_t roB = 10240u + (uint32_t)((wn + lmr) * 80) + lmc;  // + g*1280  + kt*32

    const int fr = tid >> 2, fc = tid & 3;   // fill rows 0..63 (+64), chunks 0..3

    auto fill = [&](int st, int k0) {
        uint32_t sb = sbase + st * GSTAGE;
        #pragma unroll
        for (int l = 0; l < 2; l++) {
            int r = fr + l * 64;
            uint32_t o = (uint32_t)(r * 80 + fc * 16);
            cp16(sb + o,          &A[(size_t)(m0 + r) * Kdim + k0 + fc * 8]);
            cp16(sb + 10240 + o,  &B[(size_t)(n0 + r) * Kdim + k0 + fc * 8]);
        }
    };

    fill(0, 0);  CP_COMMIT();
    fill(1, 32); CP_COMMIT();

    for (int t = 0; t < GEMM_NT; t++) {
        if (t + 2 < GEMM_NT) CP_WAIT1(); else CP_WAIT0();
        __syncthreads();
        if (t + 2 < GEMM_NT) { fill((t + 2) % 3, (t + 2) * 32); CP_COMMIT(); }

        const uint32_t sb = sbase + (t % 3) * GSTAGE;

        // load ALL fragments for both kt up front
        uint32_t a[2][2][4];        // [kt][mi]
        uint32_t b[2][8][2];        // [kt][ni]
        #pragma unroll
        for (int kt = 0; kt < 2; kt++) {
            #pragma unroll
            for (int mi = 0; mi < 2; mi++)
                ldsm4(a[kt][mi], sb + roA + mi * 1280 + kt * 32);
            #pragma unroll
            for (int g = 0; g < 4; g++) {
                uint32_t tt[4];
                ldsm4(tt, sb + roB + g * 1280 + kt * 32);
                b[kt][2*g][0] = tt[0]; b[kt][2*g][1] = tt[2];
                b[kt][2*g+1][0] = tt[1]; b[kt][2*g+1][1] = tt[3];
            }
        }
        // 32 independent MMAs
        #pragma unroll
        for (int kt = 0; kt < 2; kt++)
            #pragma unroll
            for (int mi = 0; mi < 2; mi++)
                #pragma unroll
                for (int ni = 0; ni < 8; ni++)
                    mma_f16(acc[mi][ni], a[kt][mi], b[kt][ni]);
    }

    // epilogue
    #pragma unroll
    for (int mi = 0; mi < 2; mi++) {
        int r0 = m0 + wm + mi * 16 + (lane >> 2);
        #pragma unroll
        for (int ni = 0; ni < 8; ni++) {
            int col = n0 + wn + ni * 8 + 2 * (lane & 3);
            float b0 = bias[col], b1 = bias[col + 1];
            #pragma unroll
            for (int rr = 0; rr < 2; rr++) {
                int row = r0 + rr * 8;
                float v0 = acc[mi][ni][rr * 2 + 0] + b0;
                float v1 = acc[mi][ni][rr * 2 + 1] + b1;
                if (MODE == 0) {
                    *(float2*)&C[(size_t)row * Nc + col] = make_float2(v0, v1);
                } else {
                    int bb = row >> 11, nn = row & 2047;
                    int which = col >> 10, rem = col & 1023;
                    int hh = rem >> 6, dd = rem & 63;
                    if (which == 0) { v0 *= SCALE; v1 *= SCALE; }
                    size_t idx = (((size_t)(bb * Hh + hh)) * Nseq + nn) * HD + dd;
                    __half* dst = (which == 0) ? g_q : (which == 1) ? g_k : g_v;
                    *(__half2*)&dst[idx] = __floats2half2_rn(v0, v1);
                }
            }
        }
    }
}

// ---------------- flash attention: fp16, cp.async 3-stage (R10 config) -------
// 8 warps, Q-tile 128 (Q in registers), K-tile 64. Rows 128B fp16, pitch 144B.
#define FSTAGE 18432
#define FLASH_DSMEM (3 * FSTAGE + 3 * 256)
#define FLASH_NT (Nseq / 64)

__global__ void __launch_bounds__(256) flash_mma(const float* __restrict__ attn_bias) {
    extern __shared__ char dyn[];
    const uint32_t sbase = smem_u32(dyn);
    const uint32_t sbias = sbase + 3 * FSTAGE;

    const int tid = threadIdx.x, lane = tid & 31, wid = tid >> 5;
    const int b = blockIdx.z, h = blockIdx.y, q0 = blockIdx.x * 128;
    const size_t hoff = (size_t)((b * Hh + h) * Nseq) * HD;
    const __half *Qp = g_q + hoff, *Kp = g_k + hoff, *Vp = g_v + hoff;
    const float* biasg = attn_bias + b * Nseq;

    const int fr = tid >> 3, fc = tid & 7;   // row base (0..31), 16B chunk (0..7)

    auto fill = [&](int st, int k0) {
        uint32_t sb = sbase + st * FSTAGE;
        #pragma unroll
        for (int half = 0; half < 2; half++) {
            int r = fr + half * 32;
            uint32_t o = (uint32_t)(r * 144 + fc * 16);
            size_t g = (size_t)(k0 + r) * HD + fc * 8;
            cp16(sb + o,        &Kp[g]);
            cp16(sb + 9216 + o, &Vp[g]);
        }
        if (tid < 16) cp16(sbias + st * 256 + tid * 16, &biasg[k0 + tid * 4]);
    };

    // ---- Q A-fragments directly from gmem ----
    uint32_t qf[4][4];
    {
        int r = q0 + wid * 16 + (lane >> 2);
        int c = 2 * (lane & 3);
        #pragma unroll
        for (int kf = 0; kf < 4; kf++) {
            #pragma unroll
            for (int e = 0; e < 4; e++) {
                size_t g = (size_t)(r + (e & 1) * 8) * HD + kf * 16 + (e >> 1) * 8 + c;
                qf[kf][e] = *(const uint32_t*)&Qp[g];
            }
        }
    }

    fill(0, 0);  CP_COMMIT();
    fill(1, 64); CP_COMMIT();

    float O[8][4] = {};
    float mrow0 = -1e30f, mrow1 = -1e30f, lrow0 = 0.f, lrow1 = 0.f;

    for (int t = 0; t < FLASH_NT; t++) {
        if (t + 2 < FLASH_NT) CP_WAIT1(); else CP_WAIT0();
        __syncthreads();
        if (t + 2 < FLASH_NT) { fill((t + 2) % 3, (t + 2) * 64); CP_COMMIT(); }

        const uint32_t sb = sbase + (t % 3) * FSTAGE;
        const uint32_t aK = sb, aV = sb + 9216;
        const float* sB = (const float*)(dyn + 3 * FSTAGE + (t % 3) * 256);

        // ---- S = Q K^T ----
        float S[8][4] = {};
        #pragma unroll
        for (int kf = 0; kf < 4; kf++) {
            #pragma unroll
            for (int g = 0; g < 4; g++) {
                uint32_t ro = (uint32_t)((g * 16 + (lane & 15)) * 144 + kf * 32 + (lane >> 4) * 16);
                uint32_t tt[4], b0[2], b1[2];
                ldsm4(tt, aK + ro);
                b0[0] = tt[0]; b0[1] = tt[2]; b1[0] = tt[1]; b1[1] = tt[3];
                mma_f16(S[2*g],   qf[kf], b0);
                mma_f16(S[2*g+1], qf[kf], b1);
            }
        }

        // ---- bias + online softmax ----
        float mx0 = mrow0, mx1 = mrow1;
        #pragma unroll
        for (int nt = 0; nt < 8; nt++) {
            float2 bb = *(const float2*)&sB[nt * 8 + 2 * (lane & 3)];
            S[nt][0] += bb.x; S[nt][1] += bb.y;
            S[nt][2] += bb.x; S[nt][3] += bb.y;
            mx0 = fmaxf(mx0, fmaxf(S[nt][0], S[nt][1]));
            mx1 = fmaxf(mx1, fmaxf(S[nt][2], S[nt][3]));
        }
        mx0 = fmaxf(mx0, __shfl_xor_sync(0xffffffffu, mx0, 1));
        mx0 = fmaxf(mx0, __shfl_xor_sync(0xffffffffu, mx0, 2));
        mx1 = fmaxf(mx1, __shfl_xor_sync(0xffffffffu, mx1, 1));
        mx1 = fmaxf(mx1, __shfl_xor_sync(0xffffffffu, mx1, 2));
        float alpha0 = __expf(mrow0 - mx0), alpha1 = __expf(mrow1 - mx1);
        mrow0 = mx0; mrow1 = mx1;
        float sum0 = 0.f, sum1 = 0.f;
        #pragma unroll
        for (int nt = 0; nt < 8; nt++) {
            S[nt][0] = __expf(S[nt][0] - mx0); S[nt][1] = __expf(S[nt][1] - mx0);
            S[nt][2] = __expf(S[nt][2] - mx1); S[nt][3] = __expf(S[nt][3] - mx1);
            sum0 += S[nt][0] + S[nt][1];
            sum1 += S[nt][2] + S[nt][3];
        }
        sum0 += __shfl_xor_sync(0xffffffffu, sum0, 1);
        sum0 += __shfl_xor_sync(0xffffffffu, sum0, 2);
        sum1 += __shfl_xor_sync(0xffffffffu, sum1, 1);
        sum1 += __shfl_xor_sync(0xffffffffu, sum1, 2);
        lrow0 = lrow0 * alpha0 + sum0;
        lrow1 = lrow1 * alpha1 + sum1;
        #pragma unroll
        for (int dt = 0; dt < 8; dt++) {
            O[dt][0] *= alpha0; O[dt][1] *= alpha0;
            O[dt][2] *= alpha1; O[dt][3] *= alpha1;
        }

        // ---- P -> fp16 A-fragments ----
        uint32_t pf[4][4];
        #pragma unroll
        for (int kt = 0; kt < 4; kt++) {
            #pragma unroll
            for (int half = 0; half < 2; half++) {
                int nt = 2 * kt + half;
                pf[kt][half * 2 + 0] = pack_f16(S[nt][0], S[nt][1]);
                pf[kt][half * 2 + 1] = pack_f16(S[nt][2], S[nt][3]);
            }
        }

        // ---- O += P V ----
        #pragma unroll
        for (int kt = 0; kt < 4; kt++) {
            #pragma unroll
            for (int g = 0; g < 4; g++) {
                uint32_t ro = (uint32_t)((kt * 16 + (lane & 7) + 8 * ((lane >> 3) & 1)) * 144
                                         + g * 32 + (lane >> 4) * 16);
                uint32_t tt[4], v0[2], v1[2];
                ldsm4t(tt, aV + ro);
                v0[0] = tt[0]; v0[1] = tt[1]; v1[0] = tt[2]; v1[1] = tt[3];
                mma_f16(O[2*g],   pf[kt], v0);
                mma_f16(O[2*g+1], pf[kt], v1);
            }
        }
    }

    // ---- epilogue: normalize, write fp16 attention output ----
    float inv0 = 1.f / lrow0, inv1 = 1.f / lrow1;
    int r0 = q0 + wid * 16 + (lane >> 2);
    #pragma unroll
    for (int dt = 0; dt < 8; dt++) {
        int col = h * HD + dt * 8 + 2 * (lane & 3);
        size_t i0 = (size_t)(b * Nseq + r0) * Dm + col;
        size_t i1 = (size_t)(b * Nseq + r0 + 8) * Dm + col;
        *(__half2*)&g_a[i0] = __floats2half2_rn(O[dt][0] * inv0, O[dt][1] * inv0);
        *(__half2*)&g_a[i1] = __floats2half2_rn(O[dt][2] * inv1, O[dt][3] * inv1);
    }
}

// ---------------- launch -----------------------------------------------------
extern "C" void kernel_launch(void* const* d_in, const int* in_sizes, int n_in,
                              void* d_out, int out_size)
{
    const float* x         = (const float*)d_in[0];
    const float* attn_bias = (const float*)d_in[1];
    const float* w_qkv     = (const float*)d_in[2];
    const float* b_qkv     = (const float*)d_in[3];
    const float* w_proj    = (const float*)d_in[4];
    const float* b_proj    = (const float*)d_in[5];
    float* out = (float*)d_out;

    cudaFuncSetAttribute(mma_gemm<1>, cudaFuncAttributeMaxDynamicSharedMemorySize, GEMM_DSMEM);
    cudaFuncSetAttribute(mma_gemm<0>, cudaFuncAttributeMaxDynamicSharedMemorySize, GEMM_DSMEM);
    cudaFuncSetAttribute(flash_mma,   cudaFuncAttributeMaxDynamicSharedMemorySize, FLASH_DSMEM);

    conv_x_kernel<<<(Bd * Nseq * Dm) / (256 * 4), 256>>>(x);
    convT_kernel<0><<<dim3(3 * Dm / 32, Kdim / 32), 256>>>(w_qkv, 3 * Dm);
    convT_kernel<1><<<dim3(Dm / 32, Kdim / 32), 256>>>(w_proj, Dm);

    mma_gemm<1><<<dim3(3 * Dm / 128, (Bd * Nseq) / 128), 256, GEMM_DSMEM>>>(b_qkv, nullptr, 3 * Dm);

    flash_mma<<<dim3(Nseq / 128, Hh, Bd), 256, FLASH_DSMEM>>>(attn_bias);

    mma_gemm<0><<<dim3(Dm / 128, (Bd * Nseq) / 128), 256, GEMM_DSMEM>>>(b_proj, out, Dm);
}

// round 13
// speedup vs baseline: 1.0261x; 1.0189x over previous
#include <cuda_runtime.h>
#include <cuda_fp16.h>
#include <stdint.h>

// Problem constants
#define Bd   2
#define Nseq 2048
#define Dm   1024
#define Hh   16
#define HD   64
#define SCALE 0.125f
#define Kdim 1024

// ---------------- device scratch (no allocations allowed) -------------------
__device__ __half g_x[Bd*Nseq*Dm];          // x fp16
__device__ __half g_wq[3*Dm*Kdim];          // w_qkv^T fp16 [3072,1024]
__device__ __half g_wp[Dm*Kdim];            // w_proj^T fp16 [1024,1024]
__device__ __half g_q[Bd*Hh*Nseq*HD];       // q*scale fp16 [B,H,N,64]
__device__ __half g_k[Bd*Hh*Nseq*HD];
__device__ __half g_v[Bd*Hh*Nseq*HD];
__device__ __half g_a[Bd*Nseq*Dm];          // attention out fp16

// ---------------- helpers ----------------------------------------------------
__device__ __forceinline__ uint32_t smem_u32(const void* p) {
    return (uint32_t)__cvta_generic_to_shared(p);
}
__device__ __forceinline__ void mma_f16(float (&d)[4], const uint32_t (&a)[4],
                                        const uint32_t (&b)[2]) {
    asm volatile(
        "mma.sync.aligned.m16n8k16.row.col.f32.f16.f16.f32 "
        "{%0,%1,%2,%3}, {%4,%5,%6,%7}, {%8,%9}, {%0,%1,%2,%3};"
        : "+f"(d[0]), "+f"(d[1]), "+f"(d[2]), "+f"(d[3])
        : "r"(a[0]), "r"(a[1]), "r"(a[2]), "r"(a[3]), "r"(b[0]), "r"(b[1]));
}
__device__ __forceinline__ void ldsm4(uint32_t (&r)[4], uint32_t addr) {
    asm volatile("ldmatrix.sync.aligned.m8n8.x4.shared.b16 {%0,%1,%2,%3}, [%4];"
        : "=r"(r[0]), "=r"(r[1]), "=r"(r[2]), "=r"(r[3]) : "r"(addr));
}
__device__ __forceinline__ void ldsm4t(uint32_t (&r)[4], uint32_t addr) {
    asm volatile("ldmatrix.sync.aligned.m8n8.x4.trans.shared.b16 {%0,%1,%2,%3}, [%4];"
        : "=r"(r[0]), "=r"(r[1]), "=r"(r[2]), "=r"(r[3]) : "r"(addr));
}
__device__ __forceinline__ uint32_t pack_f16(float lo, float hi) {
    __half2 h = __floats2half2_rn(lo, hi);
    return *(uint32_t*)&h;
}
__device__ __forceinline__ void cp16(uint32_t s, const void* g) {
    asm volatile("cp.async.cg.shared.global [%0], [%1], 16;" :: "r"(s), "l"(g));
}
#define CP_COMMIT() asm volatile("cp.async.commit_group;" ::: "memory")
#define CP_WAIT1()  asm volatile("cp.async.wait_group 1;" ::: "memory")
#define CP_WAIT0()  asm volatile("cp.async.wait_group 0;" ::: "memory")

// ---------------- fused convert pre-pass -------------------------------------
// blocks [0, 4096)           : x fp32 -> fp16 (4 elems/thread)
// blocks [4096, 4096+3072)   : w_qkv transpose+convert (32x32 tiles)
// blocks [7168, 7168+1024)   : w_proj transpose+convert
#define CONV_XB   4096
#define CONV_QB   3072
#define CONV_PB   1024
#define CONV_BLKS (CONV_XB + CONV_QB + CONV_PB)

__global__ void __launch_bounds__(256) conv_all_kernel(
    const float* __restrict__ x, const float* __restrict__ wq,
    const float* __restrict__ wp)
{
    int bid = blockIdx.x;
    if (bid < CONV_XB) {
        int i4 = (bid * 256 + threadIdx.x) * 4;
        float4 v = *(const float4*)&x[i4];
        *(__half2*)&g_x[i4]     = __floats2half2_rn(v.x, v.y);
        *(__half2*)&g_x[i4 + 2] = __floats2half2_rn(v.z, v.w);
        return;
    }
    // transpose path
    __shared__ float t[32][33];
    const float* w;
    __half* dst;
    int N, n0, k0;
    if (bid < CONV_XB + CONV_QB) {
        int lb = bid - CONV_XB;              // 96 x 32
        w = wq; dst = g_wq; N = 3 * Dm;
        n0 = (lb % 96) * 32; k0 = (lb / 96) * 32;
    } else {
        int lb = bid - CONV_XB - CONV_QB;    // 32 x 32
        w = wp; dst = g_wp; N = Dm;
        n0 = (lb % 32) * 32; k0 = (lb / 32) * 32;
    }
    int tx = threadIdx.x & 31, ty = threadIdx.x >> 5;   // 32 x 8
    #pragma unroll
    for (int i = 0; i < 4; i++) {
        int k = k0 + ty + i * 8;
        t[ty + i * 8][tx] = w[(size_t)k * N + n0 + tx];
    }
    __syncthreads();
    #pragma unroll
    for (int i = 0; i < 4; i++) {
        int n = n0 + ty + i * 8;
        dst[(size_t)n * Kdim + k0 + tx] = __float2half_rn(t[tx][ty + i * 8]);
    }
}

// ---------------- QKV GEMM: fp16, 512 thr, 128x128 tile (R10 config) ---------
// 16 warps (4m x 4n), warp tile 32x32, K-tile 32, cp.async 3-stage.
#define GSTAGE_A 20480
#define GEMM_A_DSMEM (3 * GSTAGE_A)
#define GEMM_NT (Kdim / 32)

__global__ void __launch_bounds__(512) mma_gemm_qkv(const float* __restrict__ bias) {
    extern __shared__ char dyn[];
    const uint32_t sbase = smem_u32(dyn);

    const int tid = threadIdx.x, lane = tid & 31, wid = tid >> 5;
    const int m0 = blockIdx.y * 128, n0 = blockIdx.x * 128;
    const __half* A = g_x;
    const __half* B = g_wq;
    const int wm = (wid >> 2) * 32, wn = (wid & 3) * 32;

    float acc[2][4][4] = {};

    const uint32_t lmr = (uint32_t)(lane & 15);
    const uint32_t lmc = (uint32_t)((lane >> 4) * 16);
    const int fr = tid >> 2, fc = tid & 3;   // fill: row (0..127), chunk (0..3)

    auto fill = [&](int st, int k0) {
        uint32_t sb = sbase + st * GSTAGE_A;
        uint32_t o = (uint32_t)(fr * 80 + fc * 16);
        cp16(sb + o,          &A[(size_t)(m0 + fr) * Kdim + k0 + fc * 8]);
        cp16(sb + 10240 + o,  &B[(size_t)(n0 + fr) * Kdim + k0 + fc * 8]);
    };

    fill(0, 0);  CP_COMMIT();
    fill(1, 32); CP_COMMIT();

    for (int t = 0; t < GEMM_NT; t++) {
        if (t + 2 < GEMM_NT) CP_WAIT1(); else CP_WAIT0();
        __syncthreads();
        if (t + 2 < GEMM_NT) { fill((t + 2) % 3, (t + 2) * 32); CP_COMMIT(); }

        const uint32_t sb = sbase + (t % 3) * GSTAGE_A;
        const uint32_t aA = sb, aB = sb + 10240;

        #pragma unroll
        for (int kt = 0; kt < 2; kt++) {
            uint32_t a[2][4], b[4][2];
            #pragma unroll
            for (int mi = 0; mi < 2; mi++) {
                uint32_t ro = (wm + mi * 16 + lmr) * 80 + kt * 32 + lmc;
                ldsm4(a[mi], aA + ro);
            }
            #pragma unroll
            for (int g = 0; g < 2; g++) {
                uint32_t ro = (wn + g * 16 + lmr) * 80 + kt * 32 + lmc;
                uint32_t tt[4];
                ldsm4(tt, aB + ro);
                b[2*g][0] = tt[0]; b[2*g][1] = tt[2];
                b[2*g+1][0] = tt[1]; b[2*g+1][1] = tt[3];
            }
            #pragma unroll
            for (int mi = 0; mi < 2; mi++)
                #pragma unroll
                for (int ni = 0; ni < 4; ni++)
                    mma_f16(acc[mi][ni], a[mi], b[ni]);
        }
    }

    // epilogue: scatter q/k/v fp16 (q pre-scaled)
    #pragma unroll
    for (int mi = 0; mi < 2; mi++) {
        int r0 = m0 + wm + mi * 16 + (lane >> 2);
        #pragma unroll
        for (int ni = 0; ni < 4; ni++) {
            int col = n0 + wn + ni * 8 + 2 * (lane & 3);
            float b0 = bias[col], b1 = bias[col + 1];
            #pragma unroll
            for (int rr = 0; rr < 2; rr++) {
                int row = r0 + rr * 8;
                float v0 = acc[mi][ni][rr * 2 + 0] + b0;
                float v1 = acc[mi][ni][rr * 2 + 1] + b1;
                int bb = row >> 11, nn = row & 2047;
                int which = col >> 10, rem = col & 1023;
                int hh = rem >> 6, dd = rem & 63;
                if (which == 0) { v0 *= SCALE; v1 *= SCALE; }
                size_t idx = (((size_t)(bb * Hh + hh)) * Nseq + nn) * HD + dd;
                __half* dst = (which == 0) ? g_q : (which == 1) ? g_k : g_v;
                *(__half2*)&dst[idx] = __floats2half2_rn(v0, v1);
            }
        }
    }
}

// ---------------- proj GEMM: fp16, 256 thr, 128x64 tile, 3 CTA/SM ------------
// 8 warps (4m x 2n), warp tile 32x32, K-tile 32, cp.async 3-stage.
#define GSTAGE_B 15360
#define GEMM_B_DSMEM (3 * GSTAGE_B)

__global__ void __launch_bounds__(256, 3) mma_gemm_proj(const float* __restrict__ bias,
                                                        float* __restrict__ C) {
    extern __shared__ char dyn[];
    const uint32_t sbase = smem_u32(dyn);

    const int tid = threadIdx.x, lane = tid & 31, wid = tid >> 5;
    const int m0 = blockIdx.y * 128, n0 = blockIdx.x * 64;
    const __half* A = g_a;
    const __half* B = g_wp;
    const int wm = (wid >> 1) * 32, wn = (wid & 1) * 32;

    float acc[2][4][4] = {};

    const uint32_t lmr = (uint32_t)(lane & 15);
    const uint32_t lmc = (uint32_t)((lane >> 4) * 16);

    auto fill = [&](int st, int k0) {
        uint32_t sb = sbase + st * GSTAGE_B;
        #pragma unroll
        for (int l = 0; l < 3; l++) {
            int s = tid + l * 256;
            int r = s >> 2, c = s & 3;
            if (r < 128) {
                cp16(sb + (uint32_t)(r * 80 + c * 16),
                     &A[(size_t)(m0 + r) * Kdim + k0 + c * 8]);
            } else {
                cp16(sb + 10240 + (uint32_t)((r - 128) * 80 + c * 16),
                     &B[(size_t)(n0 + r - 128) * Kdim + k0 + c * 8]);
            }
        }
    };

    fill(0, 0);  CP_COMMIT();
    fill(1, 32); CP_COMMIT();

    for (int t = 0; t < GEMM_NT; t++) {
        if (t + 2 < GEMM_NT) CP_WAIT1(); else CP_WAIT0();
        __syncthreads();
        if (t + 2 < GEMM_NT) { fill((t + 2) % 3, (t + 2) * 32); CP_COMMIT(); }

        const uint32_t sb = sbase + (t % 3) * GSTAGE_B;
        const uint32_t aA = sb, aB = sb + 10240;

        #pragma unroll
        for (int kt = 0; kt < 2; kt++) {
            uint32_t a[2][4], b[4][2];
            #pragma unroll
            for (int mi = 0; mi < 2; mi++) {
                uint32_t ro = (wm + mi * 16 + lmr) * 80 + kt * 32 + lmc;
                ldsm4(a[mi], aA + ro);
            }
            #pragma unroll
            for (int g = 0; g < 2; g++) {
                uint32_t ro = (wn + g * 16 + lmr) * 80 + kt * 32 + lmc;
                uint32_t tt[4];
                ldsm4(tt, aB + ro);
                b[2*g][0] = tt[0]; b[2*g][1] = tt[2];
                b[2*g+1][0] = tt[1]; b[2*g+1][1] = tt[3];
            }
            #pragma unroll
            for (int mi = 0; mi < 2; mi++)
                #pragma unroll
                for (int ni = 0; ni < 4; ni++)
                    mma_f16(acc[mi][ni], a[mi], b[ni]);
        }
    }

    // epilogue: fp32 output + bias
    #pragma unroll
    for (int mi = 0; mi < 2; mi++) {
        int r0 = m0 + wm + mi * 16 + (lane >> 2);
        #pragma unroll
        for (int ni = 0; ni < 4; ni++) {
            int col = n0 + wn + ni * 8 + 2 * (lane & 3);
            float b0 = bias[col], b1 = bias[col + 1];
            #pragma unroll
            for (int rr = 0; rr < 2; rr++) {
                int row = r0 + rr * 8;
                float v0 = acc[mi][ni][rr * 2 + 0] + b0;
                float v1 = acc[mi][ni][rr * 2 + 1] + b1;
                *(float2*)&C[(size_t)row * Dm + col] = make_float2(v0, v1);
            }
        }
    }
}

// ---------------- flash attention: fp16, cp.async 3-stage (R10 config) -------
// 8 warps, Q-tile 128 (Q in registers), K-tile 64. Rows 128B fp16, pitch 144B.
#define FSTAGE 18432
#define FLASH_DSMEM (3 * FSTAGE + 3 * 256)
#define FLASH_NT (Nseq / 64)

__global__ void __launch_bounds__(256) flash_mma(const float* __restrict__ attn_bias) {
    extern __shared__ char dyn[];
    const uint32_t sbase = smem_u32(dyn);
    const uint32_t sbias = sbase + 3 * FSTAGE;

    const int tid = threadIdx.x, lane = tid & 31, wid = tid >> 5;
    const int b = blockIdx.z, h = blockIdx.y, q0 = blockIdx.x * 128;
    const size_t hoff = (size_t)((b * Hh + h) * Nseq) * HD;
    const __half *Qp = g_q + hoff, *Kp = g_k + hoff, *Vp = g_v + hoff;
    const float* biasg = attn_bias + b * Nseq;

    const int fr = tid >> 3, fc = tid & 7;   // row base (0..31), 16B chunk (0..7)

    auto fill = [&](int st, int k0) {
        uint32_t sb = sbase + st * FSTAGE;
        #pragma unroll
        for (int half = 0; half < 2; half++) {
            int r = fr + half * 32;
            uint32_t o = (uint32_t)(r * 144 + fc * 16);
            size_t g = (size_t)(k0 + r) * HD + fc * 8;
            cp16(sb + o,        &Kp[g]);
            cp16(sb + 9216 + o, &Vp[g]);
        }
        if (tid < 16) cp16(sbias + st * 256 + tid * 16, &biasg[k0 + tid * 4]);
    };

    // ---- Q A-fragments directly from gmem ----
    uint32_t qf[4][4];
    {
        int r = q0 + wid * 16 + (lane >> 2);
        int c = 2 * (lane & 3);
        #pragma unroll
        for (int kf = 0; kf < 4; kf++) {
            #pragma unroll
            for (int e = 0; e < 4; e++) {
                size_t g = (size_t)(r + (e & 1) * 8) * HD + kf * 16 + (e >> 1) * 8 + c;
                qf[kf][e] = *(const uint32_t*)&Qp[g];
            }
        }
    }

    fill(0, 0);  CP_COMMIT();
    fill(1, 64); CP_COMMIT();

    float O[8][4] = {};
    float mrow0 = -1e30f, mrow1 = -1e30f, lrow0 = 0.f, lrow1 = 0.f;

    for (int t = 0; t < FLASH_NT; t++) {
        if (t + 2 < FLASH_NT) CP_WAIT1(); else CP_WAIT0();
        __syncthreads();
        if (t + 2 < FLASH_NT) { fill((t + 2) % 3, (t + 2) * 64); CP_COMMIT(); }

        const uint32_t sb = sbase + (t % 3) * FSTAGE;
        const uint32_t aK = sb, aV = sb + 9216;
        const float* sB = (const float*)(dyn + 3 * FSTAGE + (t % 3) * 256);

        // ---- S = Q K^T ----
        float S[8][4] = {};
        #pragma unroll
        for (int kf = 0; kf < 4; kf++) {
            #pragma unroll
            for (int g = 0; g < 4; g++) {
                uint32_t ro = (uint32_t)((g * 16 + (lane & 15)) * 144 + kf * 32 + (lane >> 4) * 16);
                uint32_t tt[4], b0[2], b1[2];
                ldsm4(tt, aK + ro);
                b0[0] = tt[0]; b0[1] = tt[2]; b1[0] = tt[1]; b1[1] = tt[3];
                mma_f16(S[2*g],   qf[kf], b0);
                mma_f16(S[2*g+1], qf[kf], b1);
            }
        }

        // ---- bias + online softmax ----
        float mx0 = mrow0, mx1 = mrow1;
        #pragma unroll
        for (int nt = 0; nt < 8; nt++) {
            float2 bb = *(const float2*)&sB[nt * 8 + 2 * (lane & 3)];
            S[nt][0] += bb.x; S[nt][1] += bb.y;
            S[nt][2] += bb.x; S[nt][3] += bb.y;
            mx0 = fmaxf(mx0, fmaxf(S[nt][0], S[nt][1]));
            mx1 = fmaxf(mx1, fmaxf(S[nt][2], S[nt][3]));
        }
        mx0 = fmaxf(mx0, __shfl_xor_sync(0xffffffffu, mx0, 1));
        mx0 = fmaxf(mx0, __shfl_xor_sync(0xffffffffu, mx0, 2));
        mx1 = fmaxf(mx1, __shfl_xor_sync(0xffffffffu, mx1, 1));
        mx1 = fmaxf(mx1, __shfl_xor_sync(0xffffffffu, mx1, 2));
        float alpha0 = __expf(mrow0 - mx0), alpha1 = __expf(mrow1 - mx1);
        mrow0 = mx0; mrow1 = mx1;
        float sum0 = 0.f, sum1 = 0.f;
        #pragma unroll
        for (int nt = 0; nt < 8; nt++) {
            S[nt][0] = __expf(S[nt][0] - mx0); S[nt][1] = __expf(S[nt][1] - mx0);
            S[nt][2] = __expf(S[nt][2] - mx1); S[nt][3] = __expf(S[nt][3] - mx1);
            sum0 += S[nt][0] + S[nt][1];
            sum1 += S[nt][2] + S[nt][3];
        }
        sum0 += __shfl_xor_sync(0xffffffffu, sum0, 1);
        sum0 += __shfl_xor_sync(0xffffffffu, sum0, 2);
        sum1 += __shfl_xor_sync(0xffffffffu, sum1, 1);
        sum1 += __shfl_xor_sync(0xffffffffu, sum1, 2);
        lrow0 = lrow0 * alpha0 + sum0;
        lrow1 = lrow1 * alpha1 + sum1;
        #pragma unroll
        for (int dt = 0; dt < 8; dt++) {
            O[dt][0] *= alpha0; O[dt][1] *= alpha0;
            O[dt][2] *= alpha1; O[dt][3] *= alpha1;
        }

        // ---- P -> fp16 A-fragments ----
        uint32_t pf[4][4];
        #pragma unroll
        for (int kt = 0; kt < 4; kt++) {
            #pragma unroll
            for (int half = 0; half < 2; half++) {
                int nt = 2 * kt + half;
                pf[kt][half * 2 + 0] = pack_f16(S[nt][0], S[nt][1]);
                pf[kt][half * 2 + 1] = pack_f16(S[nt][2], S[nt][3]);
            }
        }

        // ---- O += P V ----
        #pragma unroll
        for (int kt = 0; kt < 4; kt++) {
            #pragma unroll
            for (int g = 0; g < 4; g++) {
                uint32_t ro = (uint32_t)((kt * 16 + (lane & 7) + 8 * ((lane >> 3) & 1)) * 144
                                         + g * 32 + (lane >> 4) * 16);
                uint32_t tt[4], v0[2], v1[2];
                ldsm4t(tt, aV + ro);
                v0[0] = tt[0]; v0[1] = tt[1]; v1[0] = tt[2]; v1[1] = tt[3];
                mma_f16(O[2*g],   pf[kt], v0);
                mma_f16(O[2*g+1], pf[kt], v1);
            }
        }
    }

    // ---- epilogue: normalize, write fp16 attention output ----
    float inv0 = 1.f / lrow0, inv1 = 1.f / lrow1;
    int r0 = q0 + wid * 16 + (lane >> 2);
    #pragma unroll
    for (int dt = 0; dt < 8; dt++) {
        int col = h * HD + dt * 8 + 2 * (lane & 3);
        size_t i0 = (size_t)(b * Nseq + r0) * Dm + col;
        size_t i1 = (size_t)(b * Nseq + r0 + 8) * Dm + col;
        *(__half2*)&g_a[i0] = __floats2half2_rn(O[dt][0] * inv0, O[dt][1] * inv0);
        *(__half2*)&g_a[i1] = __floats2half2_rn(O[dt][2] * inv1, O[dt][3] * inv1);
    }
}

// ---------------- launch -----------------------------------------------------
extern "C" void kernel_launch(void* const* d_in, const int* in_sizes, int n_in,
                              void* d_out, int out_size)
{
    const float* x         = (const float*)d_in[0];
    const float* attn_bias = (const float*)d_in[1];
    const float* w_qkv     = (const float*)d_in[2];
    const float* b_qkv     = (const float*)d_in[3];
    const float* w_proj    = (const float*)d_in[4];
    const float* b_proj    = (const float*)d_in[5];
    float* out = (float*)d_out;

    cudaFuncSetAttribute(mma_gemm_qkv,  cudaFuncAttributeMaxDynamicSharedMemorySize, GEMM_A_DSMEM);
    cudaFuncSetAttribute(mma_gemm_proj, cudaFuncAttributeMaxDynamicSharedMemorySize, GEMM_B_DSMEM);
    cudaFuncSetAttribute(flash_mma,     cudaFuncAttributeMaxDynamicSharedMemorySize, FLASH_DSMEM);

    // fused converts (x split + both weight transposes) in one launch
    conv_all_kernel<<<CONV_BLKS, 256>>>(x, w_qkv, w_proj);

    // QKV GEMM (512 thr, 128x128)
    mma_gemm_qkv<<<dim3(3 * Dm / 128, (Bd * Nseq) / 128), 512, GEMM_A_DSMEM>>>(b_qkv);

    // flash attention
    flash_mma<<<dim3(Nseq / 128, Hh, Bd), 256, FLASH_DSMEM>>>(attn_bias);

    // proj GEMM (256 thr, 128x64, 3 CTA/SM — finer wave tail)
    mma_gemm_proj<<<dim3(Dm / 64, (Bd * Nseq) / 128), 256, GEMM_B_DSMEM>>>(b_proj, out);
}

// round 14
// speedup vs baseline: 1.0571x; 1.0302x over previous
#include <cuda_runtime.h>
#include <cuda_fp16.h>
#include <stdint.h>

// Problem constants
#define Bd   2
#define Nseq 2048
#define Dm   1024
#define Hh   16
#define HD   64
#define SCALE 0.125f
#define Kdim 1024

// ---------------- device scratch (no allocations allowed) -------------------
__device__ __half g_x[Bd*Nseq*Dm];          // x fp16
__device__ __half g_wq[3*Dm*Kdim];          // w_qkv^T fp16 [3072,1024]
__device__ __half g_wp[Dm*Kdim];            // w_proj^T fp16 [1024,1024]
__device__ __half g_q[Bd*Hh*Nseq*HD];       // q*scale fp16 [B,H,N,64]
__device__ __half g_k[Bd*Hh*Nseq*HD];
__device__ __half g_v[Bd*Hh*Nseq*HD];
__device__ __half g_a[Bd*Nseq*Dm];          // attention out fp16

// ---------------- helpers ----------------------------------------------------
__device__ __forceinline__ uint32_t smem_u32(const void* p) {
    return (uint32_t)__cvta_generic_to_shared(p);
}
__device__ __forceinline__ void mma_f16(float (&d)[4], const uint32_t (&a)[4],
                                        const uint32_t (&b)[2]) {
    asm volatile(
        "mma.sync.aligned.m16n8k16.row.col.f32.f16.f16.f32 "
        "{%0,%1,%2,%3}, {%4,%5,%6,%7}, {%8,%9}, {%0,%1,%2,%3};"
        : "+f"(d[0]), "+f"(d[1]), "+f"(d[2]), "+f"(d[3])
        : "r"(a[0]), "r"(a[1]), "r"(a[2]), "r"(a[3]), "r"(b[0]), "r"(b[1]));
}
__device__ __forceinline__ void ldsm4(uint32_t (&r)[4], uint32_t addr) {
    asm volatile("ldmatrix.sync.aligned.m8n8.x4.shared.b16 {%0,%1,%2,%3}, [%4];"
        : "=r"(r[0]), "=r"(r[1]), "=r"(r[2]), "=r"(r[3]) : "r"(addr));
}
__device__ __forceinline__ void ldsm4t(uint32_t (&r)[4], uint32_t addr) {
    asm volatile("ldmatrix.sync.aligned.m8n8.x4.trans.shared.b16 {%0,%1,%2,%3}, [%4];"
        : "=r"(r[0]), "=r"(r[1]), "=r"(r[2]), "=r"(r[3]) : "r"(addr));
}
__device__ __forceinline__ uint32_t pack_f16(float lo, float hi) {
    __half2 h = __floats2half2_rn(lo, hi);
    return *(uint32_t*)&h;
}
__device__ __forceinline__ void cp16(uint32_t s, const void* g) {
    asm volatile("cp.async.cg.shared.global [%0], [%1], 16;" :: "r"(s), "l"(g));
}
#define CP_COMMIT() asm volatile("cp.async.commit_group;" ::: "memory")
#define CP_WAIT1()  asm volatile("cp.async.wait_group 1;" ::: "memory")
#define CP_WAIT0()  asm volatile("cp.async.wait_group 0;" ::: "memory")

// ---------------- fused convert pre-pass -------------------------------------
// blocks [0, 4096)           : x fp32 -> fp16 (4 elems/thread)
// blocks [4096, 4096+3072)   : w_qkv transpose+convert (32x32 tiles)
// blocks [7168, 7168+1024)   : w_proj transpose+convert
#define CONV_XB   4096
#define CONV_QB   3072
#define CONV_PB   1024
#define CONV_BLKS (CONV_XB + CONV_QB + CONV_PB)

__global__ void __launch_bounds__(256) conv_all_kernel(
    const float* __restrict__ x, const float* __restrict__ wq,
    const float* __restrict__ wp)
{
    int bid = blockIdx.x;
    if (bid < CONV_XB) {
        int i4 = (bid * 256 + threadIdx.x) * 4;
        float4 v = *(const float4*)&x[i4];
        *(__half2*)&g_x[i4]     = __floats2half2_rn(v.x, v.y);
        *(__half2*)&g_x[i4 + 2] = __floats2half2_rn(v.z, v.w);
        return;
    }
    // transpose path
    __shared__ float t[32][33];
    const float* w;
    __half* dst;
    int N, n0, k0;
    if (bid < CONV_XB + CONV_QB) {
        int lb = bid - CONV_XB;              // 96 x 32
        w = wq; dst = g_wq; N = 3 * Dm;
        n0 = (lb % 96) * 32; k0 = (lb / 96) * 32;
    } else {
        int lb = bid - CONV_XB - CONV_QB;    // 32 x 32
        w = wp; dst = g_wp; N = Dm;
        n0 = (lb % 32) * 32; k0 = (lb / 32) * 32;
    }
    int tx = threadIdx.x & 31, ty = threadIdx.x >> 5;   // 32 x 8
    #pragma unroll
    for (int i = 0; i < 4; i++) {
        int k = k0 + ty + i * 8;
        t[ty + i * 8][tx] = w[(size_t)k * N + n0 + tx];
    }
    __syncthreads();
    #pragma unroll
    for (int i = 0; i < 4; i++) {
        int n = n0 + ty + i * 8;
        dst[(size_t)n * Kdim + k0 + tx] = __float2half_rn(t[tx][ty + i * 8]);
    }
}

// ---------------- HMMA GEMM: fp16, 512 thr, 128x128 tile (R10 config) --------
// 16 warps (4m x 4n), warp tile 32x32, K-tile 32, cp.async 3-stage.
// MODE 1: A=g_x, B=g_wq, scatter q/k/v. MODE 0: A=g_a, B=g_wp, write fp32 C.
#define GSTAGE 20480
#define GEMM_DSMEM (3 * GSTAGE)
#define GEMM_NT (Kdim / 32)

template<int MODE>
__global__ void __launch_bounds__(512) mma_gemm(const float* __restrict__ bias,
                                                float* __restrict__ C, int Nc) {
    extern __shared__ char dyn[];
    const uint32_t sbase = smem_u32(dyn);

    const int tid = threadIdx.x, lane = tid & 31, wid = tid >> 5;
    const int m0 = blockIdx.y * 128, n0 = blockIdx.x * 128;
    const __half* A = MODE ? g_x : g_a;
    const __half* B = MODE ? g_wq : g_wp;
    const int wm = (wid >> 2) * 32, wn = (wid & 3) * 32;

    float acc[2][4][4] = {};

    const uint32_t lmr = (uint32_t)(lane & 15);
    const uint32_t lmc = (uint32_t)((lane >> 4) * 16);
    const int fr = tid >> 2, fc = tid & 3;   // fill: row (0..127), chunk (0..3)

    auto fill = [&](int st, int k0) {
        uint32_t sb = sbase + st * GSTAGE;
        uint32_t o = (uint32_t)(fr * 80 + fc * 16);
        cp16(sb + o,          &A[(size_t)(m0 + fr) * Kdim + k0 + fc * 8]);
        cp16(sb + 10240 + o,  &B[(size_t)(n0 + fr) * Kdim + k0 + fc * 8]);
    };

    fill(0, 0);  CP_COMMIT();
    fill(1, 32); CP_COMMIT();

    for (int t = 0; t < GEMM_NT; t++) {
        if (t + 2 < GEMM_NT) CP_WAIT1(); else CP_WAIT0();
        __syncthreads();
        if (t + 2 < GEMM_NT) { fill((t + 2) % 3, (t + 2) * 32); CP_COMMIT(); }

        const uint32_t sb = sbase + (t % 3) * GSTAGE;
        const uint32_t aA = sb, aB = sb + 10240;

        #pragma unroll
        for (int kt = 0; kt < 2; kt++) {
            uint32_t a[2][4], b[4][2];
            #pragma unroll
            for (int mi = 0; mi < 2; mi++) {
                uint32_t ro = (wm + mi * 16 + lmr) * 80 + kt * 32 + lmc;
                ldsm4(a[mi], aA + ro);
            }
            #pragma unroll
            for (int g = 0; g < 2; g++) {
                uint32_t ro = (wn + g * 16 + lmr) * 80 + kt * 32 + lmc;
                uint32_t tt[4];
                ldsm4(tt, aB + ro);
                b[2*g][0] = tt[0]; b[2*g][1] = tt[2];
                b[2*g+1][0] = tt[1]; b[2*g+1][1] = tt[3];
            }
            #pragma unroll
            for (int mi = 0; mi < 2; mi++)
                #pragma unroll
                for (int ni = 0; ni < 4; ni++)
                    mma_f16(acc[mi][ni], a[mi], b[ni]);
        }
    }

    // epilogue
    #pragma unroll
    for (int mi = 0; mi < 2; mi++) {
        int r0 = m0 + wm + mi * 16 + (lane >> 2);
        #pragma unroll
        for (int ni = 0; ni < 4; ni++) {
            int col = n0 + wn + ni * 8 + 2 * (lane & 3);
            float b0 = bias[col], b1 = bias[col + 1];
            #pragma unroll
            for (int rr = 0; rr < 2; rr++) {
                int row = r0 + rr * 8;
                float v0 = acc[mi][ni][rr * 2 + 0] + b0;
                float v1 = acc[mi][ni][rr * 2 + 1] + b1;
                if (MODE == 0) {
                    *(float2*)&C[(size_t)row * Nc + col] = make_float2(v0, v1);
                } else {
                    int bb = row >> 11, nn = row & 2047;
                    int which = col >> 10, rem = col & 1023;
                    int hh = rem >> 6, dd = rem & 63;
                    if (which == 0) { v0 *= SCALE; v1 *= SCALE; }
                    size_t idx = (((size_t)(bb * Hh + hh)) * Nseq + nn) * HD + dd;
                    __half* dst = (which == 0) ? g_q : (which == 1) ? g_k : g_v;
                    *(__half2*)&dst[idx] = __floats2half2_rn(v0, v1);
                }
            }
        }
    }
}

// ---------------- flash attention: fp16, cp.async 3-stage (R10 config) -------
// 8 warps, Q-tile 128 (Q in registers), K-tile 64. Rows 128B fp16, pitch 144B.
#define FSTAGE 18432
#define FLASH_DSMEM (3 * FSTAGE + 3 * 256)
#define FLASH_NT (Nseq / 64)

__global__ void __launch_bounds__(256) flash_mma(const float* __restrict__ attn_bias) {
    extern __shared__ char dyn[];
    const uint32_t sbase = smem_u32(dyn);
    const uint32_t sbias = sbase + 3 * FSTAGE;

    const int tid = threadIdx.x, lane = tid & 31, wid = tid >> 5;
    const int b = blockIdx.z, h = blockIdx.y, q0 = blockIdx.x * 128;
    const size_t hoff = (size_t)((b * Hh + h) * Nseq) * HD;
    const __half *Qp = g_q + hoff, *Kp = g_k + hoff, *Vp = g_v + hoff;
    const float* biasg = attn_bias + b * Nseq;

    const int fr = tid >> 3, fc = tid & 7;   // row base (0..31), 16B chunk (0..7)

    auto fill = [&](int st, int k0) {
        uint32_t sb = sbase + st * FSTAGE;
        #pragma unroll
        for (int half = 0; half < 2; half++) {
            int r = fr + half * 32;
            uint32_t o = (uint32_t)(r * 144 + fc * 16);
            size_t g = (size_t)(k0 + r) * HD + fc * 8;
            cp16(sb + o,        &Kp[g]);
            cp16(sb + 9216 + o, &Vp[g]);
        }
        if (tid < 16) cp16(sbias + st * 256 + tid * 16, &biasg[k0 + tid * 4]);
    };

    // ---- Q A-fragments directly from gmem ----
    uint32_t qf[4][4];
    {
        int r = q0 + wid * 16 + (lane >> 2);
        int c = 2 * (lane & 3);
        #pragma unroll
        for (int kf = 0; kf < 4; kf++) {
            #pragma unroll
            for (int e = 0; e < 4; e++) {
                size_t g = (size_t)(r + (e & 1) * 8) * HD + kf * 16 + (e >> 1) * 8 + c;
                qf[kf][e] = *(const uint32_t*)&Qp[g];
            }
        }
    }

    fill(0, 0);  CP_COMMIT();
    fill(1, 64); CP_COMMIT();

    float O[8][4] = {};
    float mrow0 = -1e30f, mrow1 = -1e30f, lrow0 = 0.f, lrow1 = 0.f;

    for (int t = 0; t < FLASH_NT; t++) {
        if (t + 2 < FLASH_NT) CP_WAIT1(); else CP_WAIT0();
        __syncthreads();
        if (t + 2 < FLASH_NT) { fill((t + 2) % 3, (t + 2) * 64); CP_COMMIT(); }

        const uint32_t sb = sbase + (t % 3) * FSTAGE;
        const uint32_t aK = sb, aV = sb + 9216;
        const float* sB = (const float*)(dyn + 3 * FSTAGE + (t % 3) * 256);

        // ---- S = Q K^T ----
        float S[8][4] = {};
        #pragma unroll
        for (int kf = 0; kf < 4; kf++) {
            #pragma unroll
            for (int g = 0; g < 4; g++) {
                uint32_t ro = (uint32_t)((g * 16 + (lane & 15)) * 144 + kf * 32 + (lane >> 4) * 16);
                uint32_t tt[4], b0[2], b1[2];
                ldsm4(tt, aK + ro);
                b0[0] = tt[0]; b0[1] = tt[2]; b1[0] = tt[1]; b1[1] = tt[3];
                mma_f16(S[2*g],   qf[kf], b0);
                mma_f16(S[2*g+1], qf[kf], b1);
            }
        }

        // ---- bias + online softmax ----
        float mx0 = mrow0, mx1 = mrow1;
        #pragma unroll
        for (int nt = 0; nt < 8; nt++) {
            float2 bb = *(const float2*)&sB[nt * 8 + 2 * (lane & 3)];
            S[nt][0] += bb.x; S[nt][1] += bb.y;
            S[nt][2] += bb.x; S[nt][3] += bb.y;
            mx0 = fmaxf(mx0, fmaxf(S[nt][0], S[nt][1]));
            mx1 = fmaxf(mx1, fmaxf(S[nt][2], S[nt][3]));
        }
        mx0 = fmaxf(mx0, __shfl_xor_sync(0xffffffffu, mx0, 1));
        mx0 = fmaxf(mx0, __shfl_xor_sync(0xffffffffu, mx0, 2));
        mx1 = fmaxf(mx1, __shfl_xor_sync(0xffffffffu, mx1, 1));
        mx1 = fmaxf(mx1, __shfl_xor_sync(0xffffffffu, mx1, 2));
        float alpha0 = __expf(mrow0 - mx0), alpha1 = __expf(mrow1 - mx1);
        mrow0 = mx0; mrow1 = mx1;
        float sum0 = 0.f, sum1 = 0.f;
        #pragma unroll
        for (int nt = 0; nt < 8; nt++) {
            S[nt][0] = __expf(S[nt][0] - mx0); S[nt][1] = __expf(S[nt][1] - mx0);
            S[nt][2] = __expf(S[nt][2] - mx1); S[nt][3] = __expf(S[nt][3] - mx1);
            sum0 += S[nt][0] + S[nt][1];
            sum1 += S[nt][2] + S[nt][3];
        }
        sum0 += __shfl_xor_sync(0xffffffffu, sum0, 1);
        sum0 += __shfl_xor_sync(0xffffffffu, sum0, 2);
        sum1 += __shfl_xor_sync(0xffffffffu, sum1, 1);
        sum1 += __shfl_xor_sync(0xffffffffu, sum1, 2);
        lrow0 = lrow0 * alpha0 + sum0;
        lrow1 = lrow1 * alpha1 + sum1;
        #pragma unroll
        for (int dt = 0; dt < 8; dt++) {
            O[dt][0] *= alpha0; O[dt][1] *= alpha0;
            O[dt][2] *= alpha1; O[dt][3] *= alpha1;
        }

        // ---- P -> fp16 A-fragments ----
        uint32_t pf[4][4];
        #pragma unroll
        for (int kt = 0; kt < 4; kt++) {
            #pragma unroll
            for (int half = 0; half < 2; half++) {
                int nt = 2 * kt + half;
                pf[kt][half * 2 + 0] = pack_f16(S[nt][0], S[nt][1]);
                pf[kt][half * 2 + 1] = pack_f16(S[nt][2], S[nt][3]);
            }
        }

        // ---- O += P V ----
        #pragma unroll
        for (int kt = 0; kt < 4; kt++) {
            #pragma unroll
            for (int g = 0; g < 4; g++) {
                uint32_t ro = (uint32_t)((kt * 16 + (lane & 7) + 8 * ((lane >> 3) & 1)) * 144
                                         + g * 32 + (lane >> 4) * 16);
                uint32_t tt[4], v0[2], v1[2];
                ldsm4t(tt, aV + ro);
                v0[0] = tt[0]; v0[1] = tt[1]; v1[0] = tt[2]; v1[1] = tt[3];
                mma_f16(O[2*g],   pf[kt], v0);
                mma_f16(O[2*g+1], pf[kt], v1);
            }
        }
    }

    // ---- epilogue: normalize, write fp16 attention output ----
    float inv0 = 1.f / lrow0, inv1 = 1.f / lrow1;
    int r0 = q0 + wid * 16 + (lane >> 2);
    #pragma unroll
    for (int dt = 0; dt < 8; dt++) {
        int col = h * HD + dt * 8 + 2 * (lane & 3);
        size_t i0 = (size_t)(b * Nseq + r0) * Dm + col;
        size_t i1 = (size_t)(b * Nseq + r0 + 8) * Dm + col;
        *(__half2*)&g_a[i0] = __floats2half2_rn(O[dt][0] * inv0, O[dt][1] * inv0);
        *(__half2*)&g_a[i1] = __floats2half2_rn(O[dt][2] * inv1, O[dt][3] * inv1);
    }
}

// ---------------- launch -----------------------------------------------------
extern "C" void kernel_launch(void* const* d_in, const int* in_sizes, int n_in,
                              void* d_out, int out_size)
{
    const float* x         = (const float*)d_in[0];
    const float* attn_bias = (const float*)d_in[1];
    const float* w_qkv     = (const float*)d_in[2];
    const float* b_qkv     = (const float*)d_in[3];
    const float* w_proj    = (const float*)d_in[4];
    const float* b_proj    = (const float*)d_in[5];
    float* out = (float*)d_out;

    cudaFuncSetAttribute(mma_gemm<1>, cudaFuncAttributeMaxDynamicSharedMemorySize, GEMM_DSMEM);
    cudaFuncSetAttribute(mma_gemm<0>, cudaFuncAttributeMaxDynamicSharedMemorySize, GEMM_DSMEM);
    cudaFuncSetAttribute(flash_mma,   cudaFuncAttributeMaxDynamicSharedMemorySize, FLASH_DSMEM);

    // fused converts (x split + both weight transposes) in one launch
    conv_all_kernel<<<CONV_BLKS, 256>>>(x, w_qkv, w_proj);

    // QKV GEMM (512 thr, 128x128)
    mma_gemm<1><<<dim3(3 * Dm / 128, (Bd * Nseq) / 128), 512, GEMM_DSMEM>>>(b_qkv, nullptr, 3 * Dm);

    // flash attention
    flash_mma<<<dim3(Nseq / 128, Hh, Bd), 256, FLASH_DSMEM>>>(attn_bias);

    // proj GEMM (512 thr, 128x128 — R10 best-measured config)
    mma_gemm<0><<<dim3(Dm / 128, (Bd * Nseq) / 128), 512, GEMM_DSMEM>>>(b_proj, out, Dm);
}

// round 15
// speedup vs baseline: 1.0595x; 1.0022x over previous
#include <cuda_runtime.h>
#include <cuda_fp16.h>
#include <stdint.h>

// Problem constants
#define Bd   2
#define Nseq 2048
#define Dm   1024
#define Hh   16
#define HD   64
#define SCALE 0.125f
#define Kdim 1024

// ---------------- device scratch (no allocations allowed) -------------------
__device__ __half g_x[Bd*Nseq*Dm];          // x fp16
__device__ __half g_wq[3*Dm*Kdim];          // w_qkv^T fp16 [3072,1024]
__device__ __half g_wp[Dm*Kdim];            // w_proj^T fp16 [1024,1024]
__device__ __half g_q[Bd*Hh*Nseq*HD];       // q*scale fp16 [B,H,N,64]
__device__ __half g_k[Bd*Hh*Nseq*HD];
__device__ __half g_v[Bd*Hh*Nseq*HD];
__device__ __half g_a[Bd*Nseq*Dm];          // attention out fp16

// ---------------- helpers ----------------------------------------------------
__device__ __forceinline__ uint32_t smem_u32(const void* p) {
    return (uint32_t)__cvta_generic_to_shared(p);
}
__device__ __forceinline__ void mma_f16(float (&d)[4], const uint32_t (&a)[4],
                                        const uint32_t (&b)[2]) {
    asm volatile(
        "mma.sync.aligned.m16n8k16.row.col.f32.f16.f16.f32 "
        "{%0,%1,%2,%3}, {%4,%5,%6,%7}, {%8,%9}, {%0,%1,%2,%3};"
        : "+f"(d[0]), "+f"(d[1]), "+f"(d[2]), "+f"(d[3])
        : "r"(a[0]), "r"(a[1]), "r"(a[2]), "r"(a[3]), "r"(b[0]), "r"(b[1]));
}
__device__ __forceinline__ void ldsm4(uint32_t (&r)[4], uint32_t addr) {
    asm volatile("ldmatrix.sync.aligned.m8n8.x4.shared.b16 {%0,%1,%2,%3}, [%4];"
        : "=r"(r[0]), "=r"(r[1]), "=r"(r[2]), "=r"(r[3]) : "r"(addr));
}
__device__ __forceinline__ void ldsm4t(uint32_t (&r)[4], uint32_t addr) {
    asm volatile("ldmatrix.sync.aligned.m8n8.x4.trans.shared.b16 {%0,%1,%2,%3}, [%4];"
        : "=r"(r[0]), "=r"(r[1]), "=r"(r[2]), "=r"(r[3]) : "r"(addr));
}
__device__ __forceinline__ uint32_t pack_f16(float lo, float hi) {
    __half2 h = __floats2half2_rn(lo, hi);
    return *(uint32_t*)&h;
}
__device__ __forceinline__ void cp16(uint32_t s, const void* g) {
    asm volatile("cp.async.cg.shared.global [%0], [%1], 16;" :: "r"(s), "l"(g));
}
#define CP_COMMIT() asm volatile("cp.async.commit_group;" ::: "memory")
#define CP_WAIT1()  asm volatile("cp.async.wait_group 1;" ::: "memory")
#define CP_WAIT0()  asm volatile("cp.async.wait_group 0;" ::: "memory")

// ---------------- fused convert pre-pass -------------------------------------
#define CONV_XB   4096
#define CONV_QB   3072
#define CONV_PB   1024
#define CONV_BLKS (CONV_XB + CONV_QB + CONV_PB)

__global__ void __launch_bounds__(256) conv_all_kernel(
    const float* __restrict__ x, const float* __restrict__ wq,
    const float* __restrict__ wp)
{
    int bid = blockIdx.x;
    if (bid < CONV_XB) {
        int i4 = (bid * 256 + threadIdx.x) * 4;
        float4 v = *(const float4*)&x[i4];
        *(__half2*)&g_x[i4]     = __floats2half2_rn(v.x, v.y);
        *(__half2*)&g_x[i4 + 2] = __floats2half2_rn(v.z, v.w);
        return;
    }
    __shared__ float t[32][33];
    const float* w;
    __half* dst;
    int N, n0, k0;
    if (bid < CONV_XB + CONV_QB) {
        int lb = bid - CONV_XB;              // 96 x 32
        w = wq; dst = g_wq; N = 3 * Dm;
        n0 = (lb % 96) * 32; k0 = (lb / 96) * 32;
    } else {
        int lb = bid - CONV_XB - CONV_QB;    // 32 x 32
        w = wp; dst = g_wp; N = Dm;
        n0 = (lb % 32) * 32; k0 = (lb / 32) * 32;
    }
    int tx = threadIdx.x & 31, ty = threadIdx.x >> 5;   // 32 x 8
    #pragma unroll
    for (int i = 0; i < 4; i++) {
        int k = k0 + ty + i * 8;
        t[ty + i * 8][tx] = w[(size_t)k * N + n0 + tx];
    }
    __syncthreads();
    #pragma unroll
    for (int i = 0; i < 4; i++) {
        int n = n0 + ty + i * 8;
        dst[(size_t)n * Kdim + k0 + tx] = __float2half_rn(t[tx][ty + i * 8]);
    }
}

// ---------------- HMMA GEMM: fp16, 512 thr, 128x128 tile, K-tile 64 ----------
// 16 warps (4m x 4n), warp tile 32x32. 2-stage cp.async; 32 MMAs + 16 LDSM
// per warp per barrier (flash-like amortization). 2 CTA/SM.
// Stage (36864 B): A[128 rows x 144B pitch] + B[128 rows x 144B pitch]
#define GSTAGE 36864
#define GEMM_DSMEM (2 * GSTAGE)
#define GEMM_NT (Kdim / 64)

template<int MODE>
__global__ void __launch_bounds__(512, 2) mma_gemm(const float* __restrict__ bias,
                                                   float* __restrict__ C, int Nc) {
    extern __shared__ char dyn[];
    const uint32_t sbase = smem_u32(dyn);

    const int tid = threadIdx.x, lane = tid & 31, wid = tid >> 5;
    const int m0 = blockIdx.y * 128, n0 = blockIdx.x * 128;
    const __half* A = MODE ? g_x : g_a;
    const __half* B = MODE ? g_wq : g_wp;
    const int wm = (wid >> 2) * 32, wn = (wid & 3) * 32;

    float acc[2][4][4] = {};

    const uint32_t lmr = (uint32_t)(lane & 15);
    const uint32_t lmc = (uint32_t)((lane >> 4) * 16);

    // fill: 2048 cp16 slots = 256 rows (128 A + 128 B) x 8 chunks; 4/thread
    auto fill = [&](int st, int k0) {
        uint32_t sb = sbase + st * GSTAGE;
        #pragma unroll
        for (int l = 0; l < 4; l++) {
            int s = tid + l * 512;
            int r = s >> 3, c = s & 7;
            if (r < 128) {
                cp16(sb + (uint32_t)(r * 144 + c * 16),
                     &A[(size_t)(m0 + r) * Kdim + k0 + c * 8]);
            } else {
                cp16(sb + 18432 + (uint32_t)((r - 128) * 144 + c * 16),
                     &B[(size_t)(n0 + r - 128) * Kdim + k0 + c * 8]);
            }
        }
    };

    fill(0, 0);
    CP_COMMIT();

    for (int t = 0; t < GEMM_NT; t++) {
        CP_WAIT0();
        __syncthreads();
        if (t + 1 < GEMM_NT) { fill((t + 1) & 1, (t + 1) * 64); CP_COMMIT(); }

        const uint32_t sb = sbase + (t & 1) * GSTAGE;
        const uint32_t aA = sb, aB = sb + 18432;

        #pragma unroll
        for (int kt = 0; kt < 4; kt++) {
            uint32_t a[2][4], b[4][2];
            #pragma unroll
            for (int mi = 0; mi < 2; mi++) {
                uint32_t ro = (wm + mi * 16 + lmr) * 144 + kt * 32 + lmc;
                ldsm4(a[mi], aA + ro);
            }
            #pragma unroll
            for (int g = 0; g < 2; g++) {
                uint32_t ro = (wn + g * 16 + lmr) * 144 + kt * 32 + lmc;
                uint32_t tt[4];
                ldsm4(tt, aB + ro);
                b[2*g][0] = tt[0]; b[2*g][1] = tt[2];
                b[2*g+1][0] = tt[1]; b[2*g+1][1] = tt[3];
            }
            #pragma unroll
            for (int mi = 0; mi < 2; mi++)
                #pragma unroll
                for (int ni = 0; ni < 4; ni++)
                    mma_f16(acc[mi][ni], a[mi], b[ni]);
        }
    }

    // epilogue
    #pragma unroll
    for (int mi = 0; mi < 2; mi++) {
        int r0 = m0 + wm + mi * 16 + (lane >> 2);
        #pragma unroll
        for (int ni = 0; ni < 4; ni++) {
            int col = n0 + wn + ni * 8 + 2 * (lane & 3);
            float b0 = bias[col], b1 = bias[col + 1];
            #pragma unroll
            for (int rr = 0; rr < 2; rr++) {
                int row = r0 + rr * 8;
                float v0 = acc[mi][ni][rr * 2 + 0] + b0;
                float v1 = acc[mi][ni][rr * 2 + 1] + b1;
                if (MODE == 0) {
                    *(float2*)&C[(size_t)row * Nc + col] = make_float2(v0, v1);
                } else {
                    int bb = row >> 11, nn = row & 2047;
                    int which = col >> 10, rem = col & 1023;
                    int hh = rem >> 6, dd = rem & 63;
                    if (which == 0) { v0 *= SCALE; v1 *= SCALE; }
                    size_t idx = (((size_t)(bb * Hh + hh)) * Nseq + nn) * HD + dd;
                    __half* dst = (which == 0) ? g_q : (which == 1) ? g_k : g_v;
                    *(__half2*)&dst[idx] = __floats2half2_rn(v0, v1);
                }
            }
        }
    }
}

// ---------------- flash attention: fp16, cp.async 3-stage (R10 config) -------
// 8 warps, Q-tile 128 (Q in registers), K-tile 64. Rows 128B fp16, pitch 144B.
#define FSTAGE 18432
#define FLASH_DSMEM (3 * FSTAGE + 3 * 256)
#define FLASH_NT (Nseq / 64)

__global__ void __launch_bounds__(256) flash_mma(const float* __restrict__ attn_bias) {
    extern __shared__ char dyn[];
    const uint32_t sbase = smem_u32(dyn);
    const uint32_t sbias = sbase + 3 * FSTAGE;

    const int tid = threadIdx.x, lane = tid & 31, wid = tid >> 5;
    const int b = blockIdx.z, h = blockIdx.y, q0 = blockIdx.x * 128;
    const size_t hoff = (size_t)((b * Hh + h) * Nseq) * HD;
    const __half *Qp = g_q + hoff, *Kp = g_k + hoff, *Vp = g_v + hoff;
    const float* biasg = attn_bias + b * Nseq;

    const int fr = tid >> 3, fc = tid & 7;   // row base (0..31), 16B chunk (0..7)

    auto fill = [&](int st, int k0) {
        uint32_t sb = sbase + st * FSTAGE;
        #pragma unroll
        for (int half = 0; half < 2; half++) {
            int r = fr + half * 32;
            uint32_t o = (uint32_t)(r * 144 + fc * 16);
            size_t g = (size_t)(k0 + r) * HD + fc * 8;
            cp16(sb + o,        &Kp[g]);
            cp16(sb + 9216 + o, &Vp[g]);
        }
        if (tid < 16) cp16(sbias + st * 256 + tid * 16, &biasg[k0 + tid * 4]);
    };

    // ---- Q A-fragments directly from gmem ----
    uint32_t qf[4][4];
    {
        int r = q0 + wid * 16 + (lane >> 2);
        int c = 2 * (lane & 3);
        #pragma unroll
        for (int kf = 0; kf < 4; kf++) {
            #pragma unroll
            for (int e = 0; e < 4; e++) {
                size_t g = (size_t)(r + (e & 1) * 8) * HD + kf * 16 + (e >> 1) * 8 + c;
                qf[kf][e] = *(const uint32_t*)&Qp[g];
            }
        }
    }

    fill(0, 0);  CP_COMMIT();
    fill(1, 64); CP_COMMIT();

    float O[8][4] = {};
    float mrow0 = -1e30f, mrow1 = -1e30f, lrow0 = 0.f, lrow1 = 0.f;

    for (int t = 0; t < FLASH_NT; t++) {
        if (t + 2 < FLASH_NT) CP_WAIT1(); else CP_WAIT0();
        __syncthreads();
        if (t + 2 < FLASH_NT) { fill((t + 2) % 3, (t + 2) * 64); CP_COMMIT(); }

        const uint32_t sb = sbase + (t % 3) * FSTAGE;
        const uint32_t aK = sb, aV = sb + 9216;
        const float* sB = (const float*)(dyn + 3 * FSTAGE + (t % 3) * 256);

        // ---- S = Q K^T ----
        float S[8][4] = {};
        #pragma unroll
        for (int kf = 0; kf < 4; kf++) {
            #pragma unroll
            for (int g = 0; g < 4; g++) {
                uint32_t ro = (uint32_t)((g * 16 + (lane & 15)) * 144 + kf * 32 + (lane >> 4) * 16);
                uint32_t tt[4], b0[2], b1[2];
                ldsm4(tt, aK + ro);
                b0[0] = tt[0]; b0[1] = tt[2]; b1[0] = tt[1]; b1[1] = tt[3];
                mma_f16(S[2*g],   qf[kf], b0);
                mma_f16(S[2*g+1], qf[kf], b1);
            }
        }

        // ---- bias + online softmax ----
        float mx0 = mrow0, mx1 = mrow1;
        #pragma unroll
        for (int nt = 0; nt < 8; nt++) {
            float2 bb = *(const float2*)&sB[nt * 8 + 2 * (lane & 3)];
            S[nt][0] += bb.x; S[nt][1] += bb.y;
            S[nt][2] += bb.x; S[nt][3] += bb.y;
            mx0 = fmaxf(mx0, fmaxf(S[nt][0], S[nt][1]));
            mx1 = fmaxf(mx1, fmaxf(S[nt][2], S[nt][3]));
        }
        mx0 = fmaxf(mx0, __shfl_xor_sync(0xffffffffu, mx0, 1));
        mx0 = fmaxf(mx0, __shfl_xor_sync(0xffffffffu, mx0, 2));
        mx1 = fmaxf(mx1, __shfl_xor_sync(0xffffffffu, mx1, 1));
        mx1 = fmaxf(mx1, __shfl_xor_sync(0xffffffffu, mx1, 2));
        float alpha0 = __expf(mrow0 - mx0), alpha1 = __expf(mrow1 - mx1);
        mrow0 = mx0; mrow1 = mx1;
        float sum0 = 0.f, sum1 = 0.f;
        #pragma unroll
        for (int nt = 0; nt < 8; nt++) {
            S[nt][0] = __expf(S[nt][0] - mx0); S[nt][1] = __expf(S[nt][1] - mx0);
            S[nt][2] = __expf(S[nt][2] - mx1); S[nt][3] = __expf(S[nt][3] - mx1);
            sum0 += S[nt][0] + S[nt][1];
            sum1 += S[nt][2] + S[nt][3];
        }
        sum0 += __shfl_xor_sync(0xffffffffu, sum0, 1);
        sum0 += __shfl_xor_sync(0xffffffffu, sum0, 2);
        sum1 += __shfl_xor_sync(0xffffffffu, sum1, 1);
        sum1 += __shfl_xor_sync(0xffffffffu, sum1, 2);
        lrow0 = lrow0 * alpha0 + sum0;
        lrow1 = lrow1 * alpha1 + sum1;
        #pragma unroll
        for (int dt = 0; dt < 8; dt++) {
            O[dt][0] *= alpha0; O[dt][1] *= alpha0;
            O[dt][2] *= alpha1; O[dt][3] *= alpha1;
        }

        // ---- P -> fp16 A-fragments ----
        uint32_t pf[4][4];
        #pragma unroll
        for (int kt = 0; kt < 4; kt++) {
            #pragma unroll
            for (int half = 0; half < 2; half++) {
                int nt = 2 * kt + half;
                pf[kt][half * 2 + 0] = pack_f16(S[nt][0], S[nt][1]);
                pf[kt][half * 2 + 1] = pack_f16(S[nt][2], S[nt][3]);
            }
        }

        // ---- O += P V ----
        #pragma unroll
        for (int kt = 0; kt < 4; kt++) {
            #pragma unroll
            for (int g = 0; g < 4; g++) {
                uint32_t ro = (uint32_t)((kt * 16 + (lane & 7) + 8 * ((lane >> 3) & 1)) * 144
                                         + g * 32 + (lane >> 4) * 16);
                uint32_t tt[4], v0[2], v1[2];
                ldsm4t(tt, aV + ro);
                v0[0] = tt[0]; v0[1] = tt[1]; v1[0] = tt[2]; v1[1] = tt[3];
                mma_f16(O[2*g],   pf[kt], v0);
                mma_f16(O[2*g+1], pf[kt], v1);
            }
        }
    }

    // ---- epilogue: normalize, write fp16 attention output ----
    float inv0 = 1.f / lrow0, inv1 = 1.f / lrow1;
    int r0 = q0 + wid * 16 + (lane >> 2);
    #pragma unroll
    for (int dt = 0; dt < 8; dt++) {
        int col = h * HD + dt * 8 + 2 * (lane & 3);
        size_t i0 = (size_t)(b * Nseq + r0) * Dm + col;
        size_t i1 = (size_t)(b * Nseq + r0 + 8) * Dm + col;
        *(__half2*)&g_a[i0] = __floats2half2_rn(O[dt][0] * inv0, O[dt][1] * inv0);
        *(__half2*)&g_a[i1] = __floats2half2_rn(O[dt][2] * inv1, O[dt][3] * inv1);
    }
}

// ---------------- launch -----------------------------------------------------
extern "C" void kernel_launch(void* const* d_in, const int* in_sizes, int n_in,
                              void* d_out, int out_size)
{
    const float* x         = (const float*)d_in[0];
    const float* attn_bias = (const float*)d_in[1];
    const float* w_qkv     = (const float*)d_in[2];
    const float* b_qkv     = (const float*)d_in[3];
    const float* w_proj    = (const float*)d_in[4];
    const float* b_proj    = (const float*)d_in[5];
    float* out = (float*)d_out;

    cudaFuncSetAttribute(mma_gemm<1>, cudaFuncAttributeMaxDynamicSharedMemorySize, GEMM_DSMEM);
    cudaFuncSetAttribute(mma_gemm<0>, cudaFuncAttributeMaxDynamicSharedMemorySize, GEMM_DSMEM);
    cudaFuncSetAttribute(flash_mma,   cudaFuncAttributeMaxDynamicSharedMemorySize, FLASH_DSMEM);

    // fused converts (x split + both weight transposes) in one launch
    conv_all_kernel<<<CONV_BLKS, 256>>>(x, w_qkv, w_proj);

    // QKV GEMM (512 thr, 128x128, K-tile 64, 2-stage)
    mma_gemm<1><<<dim3(3 * Dm / 128, (Bd * Nseq) / 128), 512, GEMM_DSMEM>>>(b_qkv, nullptr, 3 * Dm);

    // flash attention
    flash_mma<<<dim3(Nseq / 128, Hh, Bd), 256, FLASH_DSMEM>>>(attn_bias);

    // proj GEMM (same config)
    mma_gemm<0><<<dim3(Dm / 128, (Bd * Nseq) / 128), 512, GEMM_DSMEM>>>(b_proj, out, Dm);
}

// round 16
// speedup vs baseline: 1.0735x; 1.0133x over previous
#include <cuda_runtime.h>
#include <cuda_fp16.h>
#include <stdint.h>

// Problem constants
#define Bd   2
#define Nseq 2048
#define Dm   1024
#define Hh   16
#define HD   64
#define SCALE 0.125f
#define Kdim 1024

// ---------------- device scratch (no allocations allowed) -------------------
__device__ __half g_x[Bd*Nseq*Dm];          // x fp16
__device__ __half g_wq[3*Dm*Kdim];          // w_qkv^T fp16 [3072,1024]
__device__ __half g_wp[Dm*Kdim];            // w_proj^T fp16 [1024,1024]
__device__ __half g_q[Bd*Hh*Nseq*HD];       // q*scale fp16 [B,H,N,64]
__device__ __half g_k[Bd*Hh*Nseq*HD];
__device__ __half g_v[Bd*Hh*Nseq*HD];
__device__ __half g_a[Bd*Nseq*Dm];          // attention out fp16

// ---------------- helpers ----------------------------------------------------
__device__ __forceinline__ uint32_t smem_u32(const void* p) {
    return (uint32_t)__cvta_generic_to_shared(p);
}
__device__ __forceinline__ void mma_f16(float (&d)[4], const uint32_t (&a)[4],
                                        const uint32_t (&b)[2]) {
    asm volatile(
        "mma.sync.aligned.m16n8k16.row.col.f32.f16.f16.f32 "
        "{%0,%1,%2,%3}, {%4,%5,%6,%7}, {%8,%9}, {%0,%1,%2,%3};"
        : "+f"(d[0]), "+f"(d[1]), "+f"(d[2]), "+f"(d[3])
        : "r"(a[0]), "r"(a[1]), "r"(a[2]), "r"(a[3]), "r"(b[0]), "r"(b[1]));
}
__device__ __forceinline__ void ldsm4(uint32_t (&r)[4], uint32_t addr) {
    asm volatile("ldmatrix.sync.aligned.m8n8.x4.shared.b16 {%0,%1,%2,%3}, [%4];"
        : "=r"(r[0]), "=r"(r[1]), "=r"(r[2]), "=r"(r[3]) : "r"(addr));
}
__device__ __forceinline__ void ldsm4t(uint32_t (&r)[4], uint32_t addr) {
    asm volatile("ldmatrix.sync.aligned.m8n8.x4.trans.shared.b16 {%0,%1,%2,%3}, [%4];"
        : "=r"(r[0]), "=r"(r[1]), "=r"(r[2]), "=r"(r[3]) : "r"(addr));
}
__device__ __forceinline__ uint32_t pack_f16(float lo, float hi) {
    __half2 h = __floats2half2_rn(lo, hi);
    return *(uint32_t*)&h;
}
__device__ __forceinline__ void cp16(uint32_t s, const void* g) {
    asm volatile("cp.async.cg.shared.global [%0], [%1], 16;" :: "r"(s), "l"(g));
}
#define CP_COMMIT() asm volatile("cp.async.commit_group;" ::: "memory")
#define CP_WAIT1()  asm volatile("cp.async.wait_group 1;" ::: "memory")
#define CP_WAIT0()  asm volatile("cp.async.wait_group 0;" ::: "memory")

// ---------------- fused convert pre-pass -------------------------------------
#define CONV_XB   4096
#define CONV_QB   3072
#define CONV_PB   1024
#define CONV_BLKS (CONV_XB + CONV_QB + CONV_PB)

__global__ void __launch_bounds__(256) conv_all_kernel(
    const float* __restrict__ x, const float* __restrict__ wq,
    const float* __restrict__ wp)
{
    int bid = blockIdx.x;
    if (bid < CONV_XB) {
        int i4 = (bid * 256 + threadIdx.x) * 4;
        float4 v = *(const float4*)&x[i4];
        *(__half2*)&g_x[i4]     = __floats2half2_rn(v.x, v.y);
        *(__half2*)&g_x[i4 + 2] = __floats2half2_rn(v.z, v.w);
        return;
    }
    __shared__ float t[32][33];
    const float* w;
    __half* dst;
    int N, n0, k0;
    if (bid < CONV_XB + CONV_QB) {
        int lb = bid - CONV_XB;              // 96 x 32
        w = wq; dst = g_wq; N = 3 * Dm;
        n0 = (lb % 96) * 32; k0 = (lb / 96) * 32;
    } else {
        int lb = bid - CONV_XB - CONV_QB;    // 32 x 32
        w = wp; dst = g_wp; N = Dm;
        n0 = (lb % 32) * 32; k0 = (lb / 32) * 32;
    }
    int tx = threadIdx.x & 31, ty = threadIdx.x >> 5;   // 32 x 8
    #pragma unroll
    for (int i = 0; i < 4; i++) {
        int k = k0 + ty + i * 8;
        t[ty + i * 8][tx] = w[(size_t)k * N + n0 + tx];
    }
    __syncthreads();
    #pragma unroll
    for (int i = 0; i < 4; i++) {
        int n = n0 + ty + i * 8;
        dst[(size_t)n * Kdim + k0 + tx] = __float2half_rn(t[tx][ty + i * 8]);
    }
}

// ---------------- HMMA GEMM: persistent grid, K-tile 64, 2-stage -------------
// 16 warps (4m x 4n), warp tile 32x32, 128x128 block tile. 2 CTA/SM.
// Stage (36864 B): A[128 rows x 144B pitch] + B[128 rows x 144B pitch]
#define GSTAGE 36864
#define GEMM_DSMEM (2 * GSTAGE)
#define GEMM_NT (Kdim / 64)
#define PERSIST_BLKS 296

template<int MODE>
__global__ void __launch_bounds__(512, 2) mma_gemm(const float* __restrict__ bias,
                                                   float* __restrict__ C, int Nc) {
    extern __shared__ char dyn[];
    const uint32_t sbase = smem_u32(dyn);

    const int tid = threadIdx.x, lane = tid & 31, wid = tid >> 5;
    const __half* A = MODE ? g_x : g_a;
    const __half* B = MODE ? g_wq : g_wp;
    const int wm = (wid >> 2) * 32, wn = (wid & 3) * 32;
    const int ntx = Nc / 128;                       // n-tiles
    const int ntiles = ((Bd * Nseq) / 128) * ntx;   // total tiles

    const uint32_t lmr = (uint32_t)(lane & 31 & 15);
    const uint32_t lmc = (uint32_t)((lane >> 4) * 16);

    for (int tile = blockIdx.x; tile < ntiles; tile += gridDim.x) {
        const int m0 = (tile / ntx) * 128;
        const int n0 = (tile % ntx) * 128;

        float acc[2][4][4] = {};

        auto fill = [&](int st, int k0) {
            uint32_t sb = sbase + st * GSTAGE;
            #pragma unroll
            for (int l = 0; l < 4; l++) {
                int s = tid + l * 512;
                int r = s >> 3, c = s & 7;
                if (r < 128) {
                    cp16(sb + (uint32_t)(r * 144 + c * 16),
                         &A[(size_t)(m0 + r) * Kdim + k0 + c * 8]);
                } else {
                    cp16(sb + 18432 + (uint32_t)((r - 128) * 144 + c * 16),
                         &B[(size_t)(n0 + r - 128) * Kdim + k0 + c * 8]);
                }
            }
        };

        __syncthreads();   // previous tile's compute done before refilling stage 0
        fill(0, 0);
        CP_COMMIT();

        for (int t = 0; t < GEMM_NT; t++) {
            CP_WAIT0();
            __syncthreads();
            if (t + 1 < GEMM_NT) { fill((t + 1) & 1, (t + 1) * 64); CP_COMMIT(); }

            const uint32_t sb = sbase + (t & 1) * GSTAGE;
            const uint32_t aA = sb, aB = sb + 18432;

            #pragma unroll
            for (int kt = 0; kt < 4; kt++) {
                uint32_t a[2][4], b[4][2];
                #pragma unroll
                for (int mi = 0; mi < 2; mi++) {
                    uint32_t ro = (wm + mi * 16 + lmr) * 144 + kt * 32 + lmc;
                    ldsm4(a[mi], aA + ro);
                }
                #pragma unroll
                for (int g = 0; g < 2; g++) {
                    uint32_t ro = (wn + g * 16 + lmr) * 144 + kt * 32 + lmc;
                    uint32_t tt[4];
                    ldsm4(tt, aB + ro);
                    b[2*g][0] = tt[0]; b[2*g][1] = tt[2];
                    b[2*g+1][0] = tt[1]; b[2*g+1][1] = tt[3];
                }
                #pragma unroll
                for (int mi = 0; mi < 2; mi++)
                    #pragma unroll
                    for (int ni = 0; ni < 4; ni++)
                        mma_f16(acc[mi][ni], a[mi], b[ni]);
            }
        }

        // epilogue
        #pragma unroll
        for (int mi = 0; mi < 2; mi++) {
            int r0 = m0 + wm + mi * 16 + (lane >> 2);
            #pragma unroll
            for (int ni = 0; ni < 4; ni++) {
                int col = n0 + wn + ni * 8 + 2 * (lane & 3);
                float b0 = bias[col], b1 = bias[col + 1];
                #pragma unroll
                for (int rr = 0; rr < 2; rr++) {
                    int row = r0 + rr * 8;
                    float v0 = acc[mi][ni][rr * 2 + 0] + b0;
                    float v1 = acc[mi][ni][rr * 2 + 1] + b1;
                    if (MODE == 0) {
                        *(float2*)&C[(size_t)row * Nc + col] = make_float2(v0, v1);
                    } else {
                        int bb = row >> 11, nn = row & 2047;
                        int which = col >> 10, rem = col & 1023;
                        int hh = rem >> 6, dd = rem & 63;
                        if (which == 0) { v0 *= SCALE; v1 *= SCALE; }
                        size_t idx = (((size_t)(bb * Hh + hh)) * Nseq + nn) * HD + dd;
                        __half* dst = (which == 0) ? g_q : (which == 1) ? g_k : g_v;
                        *(__half2*)&dst[idx] = __floats2half2_rn(v0, v1);
                    }
                }
            }
        }
    }
}

// ---------------- flash attention: fp16, cp.async 3-stage (R10 config) -------
// 8 warps, Q-tile 128 (Q in registers), K-tile 64. Rows 128B fp16, pitch 144B.
#define FSTAGE 18432
#define FLASH_DSMEM (3 * FSTAGE + 3 * 256)
#define FLASH_NT (Nseq / 64)

__global__ void __launch_bounds__(256) flash_mma(const float* __restrict__ attn_bias) {
    extern __shared__ char dyn[];
    const uint32_t sbase = smem_u32(dyn);
    const uint32_t sbias = sbase + 3 * FSTAGE;

    const int tid = threadIdx.x, lane = tid & 31, wid = tid >> 5;
    const int b = blockIdx.z, h = blockIdx.y, q0 = blockIdx.x * 128;
    const size_t hoff = (size_t)((b * Hh + h) * Nseq) * HD;
    const __half *Qp = g_q + hoff, *Kp = g_k + hoff, *Vp = g_v + hoff;
    const float* biasg = attn_bias + b * Nseq;

    const int fr = tid >> 3, fc = tid & 7;   // row base (0..31), 16B chunk (0..7)

    auto fill = [&](int st, int k0) {
        uint32_t sb = sbase + st * FSTAGE;
        #pragma unroll
        for (int half = 0; half < 2; half++) {
            int r = fr + half * 32;
            uint32_t o = (uint32_t)(r * 144 + fc * 16);
            size_t g = (size_t)(k0 + r) * HD + fc * 8;
            cp16(sb + o,        &Kp[g]);
            cp16(sb + 9216 + o, &Vp[g]);
        }
        if (tid < 16) cp16(sbias + st * 256 + tid * 16, &biasg[k0 + tid * 4]);
    };

    // ---- Q A-fragments directly from gmem ----
    uint32_t qf[4][4];
    {
        int r = q0 + wid * 16 + (lane >> 2);
        int c = 2 * (lane & 3);
        #pragma unroll
        for (int kf = 0; kf < 4; kf++) {
            #pragma unroll
            for (int e = 0; e < 4; e++) {
                size_t g = (size_t)(r + (e & 1) * 8) * HD + kf * 16 + (e >> 1) * 8 + c;
                qf[kf][e] = *(const uint32_t*)&Qp[g];
            }
        }
    }

    fill(0, 0);  CP_COMMIT();
    fill(1, 64); CP_COMMIT();

    float O[8][4] = {};
    float mrow0 = -1e30f, mrow1 = -1e30f, lrow0 = 0.f, lrow1 = 0.f;

    for (int t = 0; t < FLASH_NT; t++) {
        if (t + 2 < FLASH_NT) CP_WAIT1(); else CP_WAIT0();
        __syncthreads();
        if (t + 2 < FLASH_NT) { fill((t + 2) % 3, (t + 2) * 64); CP_COMMIT(); }

        const uint32_t sb = sbase + (t % 3) * FSTAGE;
        const uint32_t aK = sb, aV = sb + 9216;
        const float* sB = (const float*)(dyn + 3 * FSTAGE + (t % 3) * 256);

        // ---- S = Q K^T ----
        float S[8][4] = {};
        #pragma unroll
        for (int kf = 0; kf < 4; kf++) {
            #pragma unroll
            for (int g = 0; g < 4; g++) {
                uint32_t ro = (uint32_t)((g * 16 + (lane & 15)) * 144 + kf * 32 + (lane >> 4) * 16);
                uint32_t tt[4], b0[2], b1[2];
                ldsm4(tt, aK + ro);
                b0[0] = tt[0]; b0[1] = tt[2]; b1[0] = tt[1]; b1[1] = tt[3];
                mma_f16(S[2*g],   qf[kf], b0);
                mma_f16(S[2*g+1], qf[kf], b1);
            }
        }

        // ---- bias + online softmax ----
        float mx0 = mrow0, mx1 = mrow1;
        #pragma unroll
        for (int nt = 0; nt < 8; nt++) {
            float2 bb = *(const float2*)&sB[nt * 8 + 2 * (lane & 3)];
            S[nt][0] += bb.x; S[nt][1] += bb.y;
            S[nt][2] += bb.x; S[nt][3] += bb.y;
            mx0 = fmaxf(mx0, fmaxf(S[nt][0], S[nt][1]));
            mx1 = fmaxf(mx1, fmaxf(S[nt][2], S[nt][3]));
        }
        mx0 = fmaxf(mx0, __shfl_xor_sync(0xffffffffu, mx0, 1));
        mx0 = fmaxf(mx0, __shfl_xor_sync(0xffffffffu, mx0, 2));
        mx1 = fmaxf(mx1, __shfl_xor_sync(0xffffffffu, mx1, 1));
        mx1 = fmaxf(mx1, __shfl_xor_sync(0xffffffffu, mx1, 2));
        float alpha0 = __expf(mrow0 - mx0), alpha1 = __expf(mrow1 - mx1);
        mrow0 = mx0; mrow1 = mx1;
        float sum0 = 0.f, sum1 = 0.f;
        #pragma unroll
        for (int nt = 0; nt < 8; nt++) {
            S[nt][0] = __expf(S[nt][0] - mx0); S[nt][1] = __expf(S[nt][1] - mx0);
            S[nt][2] = __expf(S[nt][2] - mx1); S[nt][3] = __expf(S[nt][3] - mx1);
            sum0 += S[nt][0] + S[nt][1];
            sum1 += S[nt][2] + S[nt][3];
        }
        sum0 += __shfl_xor_sync(0xffffffffu, sum0, 1);
        sum0 += __shfl_xor_sync(0xffffffffu, sum0, 2);
        sum1 += __shfl_xor_sync(0xffffffffu, sum1, 1);
        sum1 += __shfl_xor_sync(0xffffffffu, sum1, 2);
        lrow0 = lrow0 * alpha0 + sum0;
        lrow1 = lrow1 * alpha1 + sum1;
        #pragma unroll
        for (int dt = 0; dt < 8; dt++) {
            O[dt][0] *= alpha0; O[dt][1] *= alpha0;
            O[dt][2] *= alpha1; O[dt][3] *= alpha1;
        }

        // ---- P -> fp16 A-fragments ----
        uint32_t pf[4][4];
        #pragma unroll
        for (int kt = 0; kt < 4; kt++) {
            #pragma unroll
            for (int half = 0; half < 2; half++) {
                int nt = 2 * kt + half;
                pf[kt][half * 2 + 0] = pack_f16(S[nt][0], S[nt][1]);
                pf[kt][half * 2 + 1] = pack_f16(S[nt][2], S[nt][3]);
            }
        }

        // ---- O += P V ----
        #pragma unroll
        for (int kt = 0; kt < 4; kt++) {
            #pragma unroll
            for (int g = 0; g < 4; g++) {
                uint32_t ro = (uint32_t)((kt * 16 + (lane & 7) + 8 * ((lane >> 3) & 1)) * 144
                                         + g * 32 + (lane >> 4) * 16);
                uint32_t tt[4], v0[2], v1[2];
                ldsm4t(tt, aV + ro);
                v0[0] = tt[0]; v0[1] = tt[1]; v1[0] = tt[2]; v1[1] = tt[3];
                mma_f16(O[2*g],   pf[kt], v0);
                mma_f16(O[2*g+1], pf[kt], v1);
            }
        }
    }

    // ---- epilogue: normalize, write fp16 attention output ----
    float inv0 = 1.f / lrow0, inv1 = 1.f / lrow1;
    int r0 = q0 + wid * 16 + (lane >> 2);
    #pragma unroll
    for (int dt = 0; dt < 8; dt++) {
        int col = h * HD + dt * 8 + 2 * (lane & 3);
        size_t i0 = (size_t)(b * Nseq + r0) * Dm + col;
        size_t i1 = (size_t)(b * Nseq + r0 + 8) * Dm + col;
        *(__half2*)&g_a[i0] = __floats2half2_rn(O[dt][0] * inv0, O[dt][1] * inv0);
        *(__half2*)&g_a[i1] = __floats2half2_rn(O[dt][2] * inv1, O[dt][3] * inv1);
    }
}

// ---------------- launch -----------------------------------------------------
extern "C" void kernel_launch(void* const* d_in, const int* in_sizes, int n_in,
                              void* d_out, int out_size)
{
    const float* x         = (const float*)d_in[0];
    const float* attn_bias = (const float*)d_in[1];
    const float* w_qkv     = (const float*)d_in[2];
    const float* b_qkv     = (const float*)d_in[3];
    const float* w_proj    = (const float*)d_in[4];
    const float* b_proj    = (const float*)d_in[5];
    float* out = (float*)d_out;

    cudaFuncSetAttribute(mma_gemm<1>, cudaFuncAttributeMaxDynamicSharedMemorySize, GEMM_DSMEM);
    cudaFuncSetAttribute(mma_gemm<0>, cudaFuncAttributeMaxDynamicSharedMemorySize, GEMM_DSMEM);
    cudaFuncSetAttribute(flash_mma,   cudaFuncAttributeMaxDynamicSharedMemorySize, FLASH_DSMEM);

    // fused converts (x split + both weight transposes) in one launch
    conv_all_kernel<<<CONV_BLKS, 256>>>(x, w_qkv, w_proj);

    // QKV GEMM: persistent grid (768 tiles on 296 blocks)
    mma_gemm<1><<<PERSIST_BLKS, 512, GEMM_DSMEM>>>(b_qkv, nullptr, 3 * Dm);

    // flash attention
    flash_mma<<<dim3(Nseq / 128, Hh, Bd), 256, FLASH_DSMEM>>>(attn_bias);

    // proj GEMM: 256 tiles on 256 blocks (persistent path, single pass)
    mma_gemm<0><<<256, 512, GEMM_DSMEM>>>(b_proj, out, Dm);
}